// round 3
// baseline (speedup 1.0000x reference)
#include <cuda_runtime.h>
#include <cuda_bf16.h>
#include <cstdint>

// ---------------------------------------------------------------------------
// GAT 3-layer pipeline on GB300 (sm_103a).  R3:
//  - el/er fused into GEMM epilogue (block owns full 128-wide rows)
//  - layer-3 GEMM fused into layer-2 aggregator epilogue (h2 never stored)
//  - float4 gather + 2-shfl broadcast in aggregator
//  - 4-edge/thread atomics (MLP), memset for zero, fused prep, inline scan
// ---------------------------------------------------------------------------

#define MAXN 50176
#define MAXE 860160

__device__ int      g_cnt[MAXN];
__device__ int      g_off[MAXN + 1];
__device__ int      g_pos[MAXN];
__device__ int      g_bsum[64];
__device__ int      g_csrc[MAXE];
__device__ float    g_feat[MAXN * 128];
__device__ float    g_res [MAXN * 128];
__device__ float    g_h1  [MAXN * 128];
__device__ float    g_el  [MAXN * 4];
__device__ float    g_er  [MAXN * 4];
__device__ float    g_f3p [MAXN * 8];
__device__ float    g_er3p[MAXN * 8];
__device__ float    g_rb3 [MAXN];
__device__ uint32_t g_w1hi[128 * 32], g_w1lo[128 * 32];    // K=64  -> 32 pairs
__device__ uint32_t g_w2hi[128 * 64], g_w2lo[128 * 64];    // K=128 -> 64 pairs
__device__ uint32_t g_r2hi[128 * 64], g_r2lo[128 * 64];

// --------------------------- bf16 split helpers ----------------------------

__device__ __forceinline__ void split2(float x, float y, uint32_t& h, uint32_t& l) {
    __nv_bfloat162 hh = __floats2bfloat162_rn(x, y);          // low 16 = x
    float hx = __bfloat162float(hh.x), hy = __bfloat162float(hh.y);
    __nv_bfloat162 ll = __floats2bfloat162_rn(x - hx, y - hy);
    h = *reinterpret_cast<uint32_t*>(&hh);
    l = *reinterpret_cast<uint32_t*>(&ll);
}

__device__ __forceinline__ void mma16816(float* c, const uint32_t* a,
                                         uint32_t b0, uint32_t b1) {
    asm volatile(
        "mma.sync.aligned.m16n8k16.row.col.f32.bf16.bf16.f32 "
        "{%0,%1,%2,%3}, {%4,%5,%6,%7}, {%8,%9}, {%0,%1,%2,%3};\n"
        : "+f"(c[0]), "+f"(c[1]), "+f"(c[2]), "+f"(c[3])
        : "r"(a[0]), "r"(a[1]), "r"(a[2]), "r"(a[3]), "r"(b0), "r"(b1));
}

// fused weight split for W1 (4096 pairs), W2 (8192), rW2 (8192)
__global__ void k_prep(const float* __restrict__ W1, const float* __restrict__ W2,
                       const float* __restrict__ rW2) {
    int idx = blockIdx.x * 256 + threadIdx.x;
    const float* W;
    uint32_t *H, *L;
    int NP, local;
    if (idx < 4096)       { W = W1;  H = g_w1hi; L = g_w1lo; NP = 32; local = idx; }
    else if (idx < 12288) { W = W2;  H = g_w2hi; L = g_w2lo; NP = 64; local = idx - 4096; }
    else if (idx < 20480) { W = rW2; H = g_r2hi; L = g_r2lo; NP = 64; local = idx - 12288; }
    else return;
    int nn = local / NP, kk = local - nn * NP;
    float w0 = W[(2 * kk) * 128 + nn];
    float w1 = W[(2 * kk + 1) * 128 + nn];
    uint32_t h, l;
    split2(w0, w1, h, l);
    H[local] = h;
    L[local] = l;
}

// ------------------------------ CSR build ---------------------------------

__global__ void k_hist(const int* __restrict__ dst, int E) {
    int i = (blockIdx.x * blockDim.x + threadIdx.x) * 4;
    if (i + 3 < E) {
        int4 d = *(const int4*)(dst + i);
        atomicAdd(&g_cnt[d.x], 1);
        atomicAdd(&g_cnt[d.y], 1);
        atomicAdd(&g_cnt[d.z], 1);
        atomicAdd(&g_cnt[d.w], 1);
    } else {
        for (int j = i; j < E; j++) atomicAdd(&g_cnt[dst[j]], 1);
    }
}

// block-level exclusive scan (1024/block): local prefix in g_off, block sums
__global__ void k_blockscan(int n) {
    __shared__ int ws[32];
    int t = threadIdx.x, lane = t & 31, wid = t >> 5;
    int i = blockIdx.x * 1024 + t;
    int v = (i < n) ? g_cnt[i] : 0;
    int x = v;
    #pragma unroll
    for (int d = 1; d < 32; d <<= 1) {
        int y = __shfl_up_sync(0xffffffffu, x, d);
        if (lane >= d) x += y;
    }
    if (lane == 31) ws[wid] = x;
    __syncthreads();
    if (wid == 0) {
        int s = ws[lane];
        #pragma unroll
        for (int d = 1; d < 32; d <<= 1) {
            int y = __shfl_up_sync(0xffffffffu, s, d);
            if (lane >= d) s += y;
        }
        ws[lane] = s;
    }
    __syncthreads();
    int incl = x + (wid > 0 ? ws[wid - 1] : 0);
    if (i < n) g_off[i] = incl - v;
    if (t == 1023) g_bsum[blockIdx.x] = incl;
}

// add block prefix (computed inline from g_bsum) to local scan
__global__ void k_addoff(int n, int E) {
    __shared__ int pre_s;
    int t = threadIdx.x;
    if (t < 32) {
        int s = 0;
        for (int j = t; j < blockIdx.x; j += 32) s += g_bsum[j];
        #pragma unroll
        for (int o = 16; o > 0; o >>= 1) s += __shfl_xor_sync(0xffffffffu, s, o);
        if (t == 0) pre_s = s;
    }
    __syncthreads();
    int i = blockIdx.x * 1024 + t;
    if (i < n) {
        int o = g_off[i] + pre_s;
        g_off[i] = o;
        g_pos[i] = o;
    }
    if (blockIdx.x == 0 && t == 0) g_off[n] = E;
}

__global__ void k_scatter(const int* __restrict__ src, const int* __restrict__ dst, int E) {
    int i = (blockIdx.x * blockDim.x + threadIdx.x) * 4;
    if (i + 3 < E) {
        int4 s = *(const int4*)(src + i);
        int4 d = *(const int4*)(dst + i);
        int p0 = atomicAdd(&g_pos[d.x], 1);
        int p1 = atomicAdd(&g_pos[d.y], 1);
        int p2 = atomicAdd(&g_pos[d.z], 1);
        int p3 = atomicAdd(&g_pos[d.w], 1);
        g_csrc[p0] = s.x; g_csrc[p1] = s.y; g_csrc[p2] = s.z; g_csrc[p3] = s.w;
    } else {
        for (int j = i; j < E; j++) {
            int p = atomicAdd(&g_pos[dst[j]], 1);
            g_csrc[p] = src[j];
        }
    }
}

// ------------- tensor-core GEMM: C[M x 128] = A @ W (+ el/er) --------------
// BM=128, BK=32, 8 warps; per warp 32(M) x 64(N); bf16x2 split, fp32 accum.
// ELR: epilogue computes el/er = per-head dot of C rows with alv/arv.

template <int K, bool ELR>
__launch_bounds__(256, 2)
__global__ void k_gemm_tc(const float* __restrict__ A,
                          const uint32_t* __restrict__ Whi,
                          const uint32_t* __restrict__ Wlo,
                          float* __restrict__ C, int M,
                          const float* __restrict__ alv,
                          const float* __restrict__ arv,
                          float* __restrict__ el, float* __restrict__ er) {
    __shared__ uint32_t sAhi[128 * 20], sAlo[128 * 20];
    __shared__ uint32_t sBhi[128 * 20], sBlo[128 * 20];
    __shared__ float sEl[512], sEr[512], sAl[128], sAr[128];
    const int t = threadIdx.x;
    const int rowBase = blockIdx.x * 128;
    const int wid = t >> 5, lane = t & 31;
    const int mwarp = wid >> 1, nwarp = wid & 1;
    const int g = lane >> 2, tig = lane & 3;
    const int NP = K >> 1;

    if (ELR && t < 128) { sAl[t] = alv[t]; sAr[t] = arv[t]; }

    float c[2][8][4];
    #pragma unroll
    for (int mi = 0; mi < 2; mi++)
        #pragma unroll
        for (int ni = 0; ni < 8; ni++)
            #pragma unroll
            for (int j = 0; j < 4; j++) c[mi][ni][j] = 0.f;

    for (int k0 = 0; k0 < K; k0 += 32) {
        const int kk0 = k0 >> 1;
        #pragma unroll
        for (int i = 0; i < 4; i++) {
            int idx = t + i * 256;
            int r = idx >> 3, c4 = idx & 7;
            int gr = rowBase + r;
            float4 v = make_float4(0.f, 0.f, 0.f, 0.f);
            if (gr < M) v = *(const float4*)(A + (size_t)gr * K + k0 + c4 * 4);
            uint32_t h0, l0, h1, l1;
            split2(v.x, v.y, h0, l0);
            split2(v.z, v.w, h1, l1);
            int b = r * 20 + c4 * 2;
            sAhi[b] = h0; sAlo[b] = l0;
            sAhi[b + 1] = h1; sAlo[b + 1] = l1;
        }
        #pragma unroll
        for (int i = 0; i < 2; i++) {
            int idx = t + i * 256;
            int nn = idx >> 2, j = (idx & 3) * 4;
            uint4 vh = *(const uint4*)(Whi + nn * NP + kk0 + j);
            uint4 vl = *(const uint4*)(Wlo + nn * NP + kk0 + j);
            int b = nn * 20 + j;
            sBhi[b] = vh.x; sBhi[b + 1] = vh.y; sBhi[b + 2] = vh.z; sBhi[b + 3] = vh.w;
            sBlo[b] = vl.x; sBlo[b + 1] = vl.y; sBlo[b + 2] = vl.z; sBlo[b + 3] = vl.w;
        }
        __syncthreads();

        #pragma unroll
        for (int ks = 0; ks < 2; ks++) {
            const int ko = ks * 8;
            uint32_t ah[2][4], al_[2][4];
            #pragma unroll
            for (int mi = 0; mi < 2; mi++) {
                int base = (mwarp * 32 + mi * 16 + g) * 20 + ko + tig;
                ah[mi][0] = sAhi[base];        al_[mi][0] = sAlo[base];
                ah[mi][1] = sAhi[base + 160];  al_[mi][1] = sAlo[base + 160];
                ah[mi][2] = sAhi[base + 4];    al_[mi][2] = sAlo[base + 4];
                ah[mi][3] = sAhi[base + 164];  al_[mi][3] = sAlo[base + 164];
            }
            #pragma unroll
            for (int ni = 0; ni < 8; ni++) {
                int bb = (nwarp * 64 + ni * 8 + g) * 20 + ko + tig;
                uint32_t bh0 = sBhi[bb], bh1 = sBhi[bb + 4];
                uint32_t bl0 = sBlo[bb], bl1 = sBlo[bb + 4];
                #pragma unroll
                for (int mi = 0; mi < 2; mi++) {
                    mma16816(c[mi][ni], ah[mi], bh0, bh1);
                    mma16816(c[mi][ni], ah[mi], bl0, bl1);
                    mma16816(c[mi][ni], al_[mi], bh0, bh1);
                }
            }
        }
        __syncthreads();
    }
    // store C
    #pragma unroll
    for (int mi = 0; mi < 2; mi++) {
        int r0 = rowBase + mwarp * 32 + mi * 16 + g;
        #pragma unroll
        for (int ni = 0; ni < 8; ni++) {
            int col = nwarp * 64 + ni * 8 + tig * 2;
            if (r0 < M)
                *(float2*)(C + (size_t)r0 * 128 + col) = make_float2(c[mi][ni][0], c[mi][ni][1]);
            if (r0 + 8 < M)
                *(float2*)(C + (size_t)(r0 + 8) * 128 + col) = make_float2(c[mi][ni][2], c[mi][ni][3]);
        }
    }
    // el/er epilogue: per row, per head dot with alv/arv.
    if (ELR) {
        #pragma unroll
        for (int mi = 0; mi < 2; mi++) {
            float pel[2][2] = {{0.f, 0.f}, {0.f, 0.f}};
            float per_[2][2] = {{0.f, 0.f}, {0.f, 0.f}};
            #pragma unroll
            for (int ni = 0; ni < 8; ni++) {
                int col = nwarp * 64 + ni * 8 + tig * 2;
                int hh = ni >> 2;
                float a0 = sAl[col], a1 = sAl[col + 1];
                float r0 = sAr[col], r1 = sAr[col + 1];
                pel[0][hh] += c[mi][ni][0] * a0 + c[mi][ni][1] * a1;
                per_[0][hh] += c[mi][ni][0] * r0 + c[mi][ni][1] * r1;
                pel[1][hh] += c[mi][ni][2] * a0 + c[mi][ni][3] * a1;
                per_[1][hh] += c[mi][ni][2] * r0 + c[mi][ni][3] * r1;
            }
            #pragma unroll
            for (int gg = 0; gg < 2; gg++)
                #pragma unroll
                for (int hh = 0; hh < 2; hh++) {
                    float v = pel[gg][hh], w = per_[gg][hh];
                    v += __shfl_xor_sync(0xffffffffu, v, 1);
                    v += __shfl_xor_sync(0xffffffffu, v, 2);
                    w += __shfl_xor_sync(0xffffffffu, w, 1);
                    w += __shfl_xor_sync(0xffffffffu, w, 2);
                    if (tig == 0) {
                        int r = mwarp * 32 + mi * 16 + g + gg * 8;
                        sEl[r * 4 + nwarp * 2 + hh] = v;
                        sEr[r * 4 + nwarp * 2 + hh] = w;
                    }
                }
        }
        __syncthreads();
        #pragma unroll
        for (int i0 = 0; i0 < 2; i0++) {
            int i = t + i0 * 256;
            int gr = rowBase + (i >> 2);
            if (gr < M) {
                el[gr * 4 + (i & 3)] = sEl[i];
                er[gr * 4 + (i & 3)] = sEr[i];
            }
        }
    }
}

// -------------- warp-per-node aggregation, H=4 D=32, 1 pass ----------------
// lane owns dims [4*lane, 4*lane+3] (head = lane>>3). If W3 != null, the
// layer-3 projection (f3 = o@W3, rb = sum(o@rW3 + b3)) is fused here and the
// 128-dim output is never written to global.

__global__ void k_agg4(const float4* __restrict__ feat4, const float* __restrict__ el,
                       const float* __restrict__ er, const float4* __restrict__ res4,
                       const float4* __restrict__ bias4, float4* __restrict__ out4,
                       const float* __restrict__ W3, const float* __restrict__ rW3,
                       const float* __restrict__ ar3, const float* __restrict__ b3,
                       float4* __restrict__ f3p4, float4* __restrict__ er3p4,
                       float* __restrict__ rb3, int n) {
    __shared__ float sW3[768], sR3[768];
    if (W3) {
        for (int i = threadIdx.x; i < 768; i += 256) { sW3[i] = W3[i]; sR3[i] = rW3[i]; }
    }
    __syncthreads();
    int node = blockIdx.x * 8 + (threadIdx.x >> 5);
    if (node >= n) return;
    int lane = threadIdx.x & 31;
    int h = lane & 3, eo = lane >> 2, h4 = lane >> 3;
    int rs = g_off[node], re = g_off[node + 1];
    float er_h = er[node * 4 + h];

    float4 acc = make_float4(0.f, 0.f, 0.f, 0.f);
    float den = 0.f;
    for (int b = rs; b < re; b += 8) {
        int e = b + eo;
        int s = -1;
        float ee = 0.f;
        if (e < re) {
            s = g_csrc[e];
            float v = el[s * 4 + h] + er_h;
            v = v > 0.f ? v : 0.2f * v;
            ee = __expf(v);
            den += ee;
        }
        #pragma unroll
        for (int q = 0; q < 8; q++) {
            int   sq = __shfl_sync(0xffffffffu, s, q * 4);
            float eq = __shfl_sync(0xffffffffu, ee, q * 4 + h4);
            if (sq < 0) break;   // warp-uniform
            float4 f = feat4[(size_t)sq * 32 + lane];
            acc.x = fmaf(eq, f.x, acc.x);
            acc.y = fmaf(eq, f.y, acc.y);
            acc.z = fmaf(eq, f.z, acc.z);
            acc.w = fmaf(eq, f.w, acc.w);
        }
    }
    den += __shfl_xor_sync(0xffffffffu, den, 16);
    den += __shfl_xor_sync(0xffffffffu, den, 8);
    den += __shfl_xor_sync(0xffffffffu, den, 4);
    float inv = 1.f / __shfl_sync(0xffffffffu, den, h4);

    float4 o;
    o.x = acc.x * inv; o.y = acc.y * inv; o.z = acc.z * inv; o.w = acc.w * inv;
    if (res4) {
        float4 r = res4[(size_t)node * 32 + lane];
        o.x += r.x; o.y += r.y; o.z += r.z; o.w += r.w;
    }
    float4 bb = bias4[lane];
    o.x = fmaxf(o.x + bb.x, 0.f);   // both 4-head layers use relu
    o.y = fmaxf(o.y + bb.y, 0.f);
    o.z = fmaxf(o.z + bb.z, 0.f);
    o.w = fmaxf(o.w + bb.w, 0.f);

    if (!W3) {
        out4[(size_t)node * 32 + lane] = o;
    } else {
        // fused layer-3 projection: p[0..5] = o·W3[:,j], p[6..11] = o·rW3[:,j]
        float p[12];
        int c0 = lane * 4;
        #pragma unroll
        for (int j = 0; j < 6; j++) {
            p[j]     = o.x * sW3[(c0 + 0) * 6 + j] + o.y * sW3[(c0 + 1) * 6 + j]
                     + o.z * sW3[(c0 + 2) * 6 + j] + o.w * sW3[(c0 + 3) * 6 + j];
            p[6 + j] = o.x * sR3[(c0 + 0) * 6 + j] + o.y * sR3[(c0 + 1) * 6 + j]
                     + o.z * sR3[(c0 + 2) * 6 + j] + o.w * sR3[(c0 + 3) * 6 + j];
        }
        #pragma unroll
        for (int j = 0; j < 12; j++) {
            #pragma unroll
            for (int ofs = 16; ofs > 0; ofs >>= 1)
                p[j] += __shfl_xor_sync(0xffffffffu, p[j], ofs);
        }
        if (lane == 0) {
            f3p4[node * 2]     = make_float4(p[0], p[1], p[2], p[3]);
            f3p4[node * 2 + 1] = make_float4(p[4], p[5], 0.f, 0.f);
            er3p4[node * 2]     = make_float4(p[0] * ar3[0], p[1] * ar3[1],
                                              p[2] * ar3[2], p[3] * ar3[3]);
            er3p4[node * 2 + 1] = make_float4(p[4] * ar3[4], p[5] * ar3[5], 0.f, 0.f);
            float rb = 0.f;
            #pragma unroll
            for (int j = 0; j < 6; j++) rb += p[6 + j] + b3[j];
            rb3[node] = rb;
        }
    }
}

// --------- layer 3 aggregation (H=6, D=1) + head mean, single pass ---------

__global__ void k_agg3(const float* __restrict__ f3p, const float* __restrict__ er3p,
                       const float* __restrict__ al3, const float* __restrict__ rbase,
                       float* __restrict__ out, int n) {
    int node = blockIdx.x * 8 + (threadIdx.x >> 5);
    if (node >= n) return;
    int lane = threadIdx.x & 31;
    int rs = g_off[node], re = g_off[node + 1];
    float al[6];
    #pragma unroll
    for (int j = 0; j < 6; j++) al[j] = al3[j];
    float4 e0 = *(const float4*)(er3p + (size_t)node * 8);
    float4 e1 = *(const float4*)(er3p + (size_t)node * 8 + 4);
    float erh[6] = {e0.x, e0.y, e0.z, e0.w, e1.x, e1.y};

    float acc[6], den[6];
    #pragma unroll
    for (int j = 0; j < 6; j++) { acc[j] = 0.f; den[j] = 0.f; }
    for (int e = rs + lane; e < re; e += 32) {
        int s = g_csrc[e];
        float4 f0 = *(const float4*)(f3p + (size_t)s * 8);
        float4 f1 = *(const float4*)(f3p + (size_t)s * 8 + 4);
        float f[6] = {f0.x, f0.y, f0.z, f0.w, f1.x, f1.y};
        #pragma unroll
        for (int j = 0; j < 6; j++) {
            float v = fmaf(f[j], al[j], erh[j]);
            v = v > 0.f ? v : 0.2f * v;
            float ee = __expf(v);
            den[j] += ee;
            acc[j] = fmaf(ee, f[j], acc[j]);
        }
    }
    #pragma unroll
    for (int j = 0; j < 6; j++) {
        #pragma unroll
        for (int o = 16; o > 0; o >>= 1) {
            acc[j] += __shfl_xor_sync(0xffffffffu, acc[j], o);
            den[j] += __shfl_xor_sync(0xffffffffu, den[j], o);
        }
    }
    if (lane == 0) {
        float o_ = 0.f;
        #pragma unroll
        for (int j = 0; j < 6; j++) o_ += acc[j] / den[j];
        out[node] = (o_ + rbase[node]) * (1.f / 6.f);
    }
}

// ------------------------------- launcher ----------------------------------

extern "C" void kernel_launch(void* const* d_in, const int* in_sizes, int n_in,
                              void* d_out, int out_size) {
    const float* x   = (const float*)d_in[0];
    const int*   src = (const int*)  d_in[1];
    const int*   dst = (const int*)  d_in[2];
    const float* W1  = (const float*)d_in[3];
    const float* al1 = (const float*)d_in[4];
    const float* ar1 = (const float*)d_in[5];
    const float* b1  = (const float*)d_in[6];
    const float* W2  = (const float*)d_in[7];
    const float* al2 = (const float*)d_in[8];
    const float* ar2 = (const float*)d_in[9];
    const float* b2  = (const float*)d_in[10];
    const float* rW2 = (const float*)d_in[11];
    const float* W3  = (const float*)d_in[12];
    const float* al3 = (const float*)d_in[13];
    const float* ar3 = (const float*)d_in[14];
    const float* b3  = (const float*)d_in[15];
    const float* rW3 = (const float*)d_in[16];
    int n = in_sizes[0] / 64;
    int E = in_sizes[1];
    float* out = (float*)d_out;

    float *feat, *res, *h1, *el, *er, *f3p, *er3p, *rb3;
    int* cnt;
    uint32_t *w1hi, *w1lo, *w2hi, *w2lo, *r2hi, *r2lo;
    cudaGetSymbolAddress((void**)&feat, g_feat);
    cudaGetSymbolAddress((void**)&res,  g_res);
    cudaGetSymbolAddress((void**)&h1,   g_h1);
    cudaGetSymbolAddress((void**)&el,   g_el);
    cudaGetSymbolAddress((void**)&er,   g_er);
    cudaGetSymbolAddress((void**)&f3p,  g_f3p);
    cudaGetSymbolAddress((void**)&er3p, g_er3p);
    cudaGetSymbolAddress((void**)&rb3,  g_rb3);
    cudaGetSymbolAddress((void**)&cnt,  g_cnt);
    cudaGetSymbolAddress((void**)&w1hi, g_w1hi);
    cudaGetSymbolAddress((void**)&w1lo, g_w1lo);
    cudaGetSymbolAddress((void**)&w2hi, g_w2hi);
    cudaGetSymbolAddress((void**)&w2lo, g_w2lo);
    cudaGetSymbolAddress((void**)&r2hi, g_r2hi);
    cudaGetSymbolAddress((void**)&r2lo, g_r2lo);

    // --- weight split (single fused kernel) ---
    k_prep<<<80, 256>>>(W1, W2, rW2);

    // --- CSR build ---
    int nb = (n + 1023) / 1024;
    cudaMemsetAsync(cnt, 0, (size_t)n * sizeof(int));
    k_hist     <<<(E + 1023) / 1024, 256>>>(dst, E);
    k_blockscan<<<nb, 1024>>>(n);
    k_addoff   <<<nb, 1024>>>(n, E);
    k_scatter  <<<(E + 1023) / 1024, 256>>>(src, dst, E);

    int gb = (n + 127) / 128;
    int ab = (n + 7) / 8;

    // --- layer 1: GEMM (+el/er) then aggregate -> h1 ---
    k_gemm_tc<64, true><<<gb, 256>>>(x, w1hi, w1lo, feat, n, al1, ar1, el, er);
    k_agg4<<<ab, 256>>>((const float4*)feat, el, er, (const float4*)nullptr,
                        (const float4*)b1, (float4*)h1,
                        nullptr, nullptr, nullptr, nullptr,
                        nullptr, nullptr, nullptr, n);

    // --- layer 2: dual GEMMs (+el/er) then aggregate with fused layer-3 proj ---
    k_gemm_tc<128, true ><<<gb, 256>>>(h1, w2hi, w2lo, feat, n, al2, ar2, el, er);
    k_gemm_tc<128, false><<<gb, 256>>>(h1, r2hi, r2lo, res, n, nullptr, nullptr,
                                       nullptr, nullptr);
    k_agg4<<<ab, 256>>>((const float4*)feat, el, er, (const float4*)res,
                        (const float4*)b2, (float4*)nullptr,
                        W3, rW3, ar3, b3,
                        (float4*)f3p, (float4*)er3p, rb3, n);

    // --- layer 3 aggregation -> output ---
    k_agg3<<<ab, 256>>>(f3p, er3p, al3, rb3, out, n);
}

// round 5
// speedup vs baseline: 1.2393x; 1.2393x over previous
#include <cuda_runtime.h>
#include <cuda_bf16.h>
#include <cstdint>

// ---------------------------------------------------------------------------
// GAT 3-layer pipeline on GB300 (sm_103a).  R4:
//  - lean warp-per-node aggregator (layer-3 fusion reverted; separate l3gemm)
//  - CSR build forked onto a side stream, overlapped with prep + GEMM1
//  - single-pass scan with lookback (one kernel instead of two)
//  - keeps: GEMM+el/er fusion, bf16x2-split tensor GEMMs, float4 gather,
//    4-edge/thread atomics, memset zeroing
// ---------------------------------------------------------------------------

#define MAXN 50176
#define MAXE 860160

__device__ int      g_cnt[MAXN];
__device__ int      g_off[MAXN + 1];
__device__ int      g_pos[MAXN];
__device__ int      g_bsum[64];
__device__ int      g_bflag[64];
__device__ int      g_csrc[MAXE];
__device__ float    g_feat[MAXN * 128];
__device__ float    g_res [MAXN * 128];
__device__ float    g_h1  [MAXN * 128];
__device__ float    g_el  [MAXN * 4];
__device__ float    g_er  [MAXN * 4];
__device__ float    g_f3p [MAXN * 8];
__device__ float    g_er3p[MAXN * 8];
__device__ float    g_rb3 [MAXN];
__device__ uint32_t g_w1hi[128 * 32], g_w1lo[128 * 32];    // K=64  -> 32 pairs
__device__ uint32_t g_w2hi[128 * 64], g_w2lo[128 * 64];    // K=128 -> 64 pairs
__device__ uint32_t g_r2hi[128 * 64], g_r2lo[128 * 64];

// --------------------------- bf16 split helpers ----------------------------

__device__ __forceinline__ void split2(float x, float y, uint32_t& h, uint32_t& l) {
    __nv_bfloat162 hh = __floats2bfloat162_rn(x, y);          // low 16 = x
    float hx = __bfloat162float(hh.x), hy = __bfloat162float(hh.y);
    __nv_bfloat162 ll = __floats2bfloat162_rn(x - hx, y - hy);
    h = *reinterpret_cast<uint32_t*>(&hh);
    l = *reinterpret_cast<uint32_t*>(&ll);
}

__device__ __forceinline__ void mma16816(float* c, const uint32_t* a,
                                         uint32_t b0, uint32_t b1) {
    asm volatile(
        "mma.sync.aligned.m16n8k16.row.col.f32.bf16.bf16.f32 "
        "{%0,%1,%2,%3}, {%4,%5,%6,%7}, {%8,%9}, {%0,%1,%2,%3};\n"
        : "+f"(c[0]), "+f"(c[1]), "+f"(c[2]), "+f"(c[3])
        : "r"(a[0]), "r"(a[1]), "r"(a[2]), "r"(a[3]), "r"(b0), "r"(b1));
}

// fused weight split for W1 (4096 pairs), W2 (8192), rW2 (8192)
__global__ void k_prep(const float* __restrict__ W1, const float* __restrict__ W2,
                       const float* __restrict__ rW2) {
    int idx = blockIdx.x * 256 + threadIdx.x;
    const float* W;
    uint32_t *H, *L;
    int NP, local;
    if (idx < 4096)       { W = W1;  H = g_w1hi; L = g_w1lo; NP = 32; local = idx; }
    else if (idx < 12288) { W = W2;  H = g_w2hi; L = g_w2lo; NP = 64; local = idx - 4096; }
    else if (idx < 20480) { W = rW2; H = g_r2hi; L = g_r2lo; NP = 64; local = idx - 12288; }
    else return;
    int nn = local / NP, kk = local - nn * NP;
    float w0 = W[(2 * kk) * 128 + nn];
    float w1 = W[(2 * kk + 1) * 128 + nn];
    uint32_t h, l;
    split2(w0, w1, h, l);
    H[local] = h;
    L[local] = l;
}

// ------------------------------ CSR build ---------------------------------

__global__ void k_hist(const int* __restrict__ dst, int E) {
    int i = (blockIdx.x * blockDim.x + threadIdx.x) * 4;
    if (i + 3 < E) {
        int4 d = *(const int4*)(dst + i);
        atomicAdd(&g_cnt[d.x], 1);
        atomicAdd(&g_cnt[d.y], 1);
        atomicAdd(&g_cnt[d.z], 1);
        atomicAdd(&g_cnt[d.w], 1);
    } else {
        for (int j = i; j < E; j++) atomicAdd(&g_cnt[dst[j]], 1);
    }
}

// single-pass exclusive scan with lookback. nb blocks (<=64), all resident.
// Each block publishes (total+1) into g_bflag; predecessors spin-read.
__global__ void k_scan2(int n, int E) {
    __shared__ int ws[32];
    __shared__ int pre_s;
    int t = threadIdx.x, lane = t & 31, wid = t >> 5, b = blockIdx.x;
    int i = b * 1024 + t;
    int v = (i < n) ? g_cnt[i] : 0;
    int x = v;
    #pragma unroll
    for (int d = 1; d < 32; d <<= 1) {
        int y = __shfl_up_sync(0xffffffffu, x, d);
        if (lane >= d) x += y;
    }
    if (lane == 31) ws[wid] = x;
    __syncthreads();
    if (wid == 0) {
        int s = ws[lane];
        #pragma unroll
        for (int d = 1; d < 32; d <<= 1) {
            int y = __shfl_up_sync(0xffffffffu, s, d);
            if (lane >= d) s += y;
        }
        ws[lane] = s;
    }
    __syncthreads();
    int incl = x + (wid > 0 ? ws[wid - 1] : 0);
    // publish block total (warp 31 holds it at t==1023)
    if (t == 1023) atomicExch(&g_bflag[b], incl + 1);
    // warp 0: lookback over predecessors
    if (wid == 0) {
        int s = 0;
        for (int j = lane; j < b; j += 32) {
            int f;
            while ((f = atomicAdd(&g_bflag[j], 0)) == 0) { }
            s += f - 1;
        }
        #pragma unroll
        for (int o = 16; o > 0; o >>= 1) s += __shfl_xor_sync(0xffffffffu, s, o);
        if (lane == 0) pre_s = s;
    }
    __syncthreads();
    if (i < n) {
        int o = incl - v + pre_s;
        g_off[i] = o;
        g_pos[i] = o;
    }
    if (b == 0 && t == 0) g_off[n] = E;
}

__global__ void k_scatter(const int* __restrict__ src, const int* __restrict__ dst, int E) {
    int i = (blockIdx.x * blockDim.x + threadIdx.x) * 4;
    if (i + 3 < E) {
        int4 s = *(const int4*)(src + i);
        int4 d = *(const int4*)(dst + i);
        int p0 = atomicAdd(&g_pos[d.x], 1);
        int p1 = atomicAdd(&g_pos[d.y], 1);
        int p2 = atomicAdd(&g_pos[d.z], 1);
        int p3 = atomicAdd(&g_pos[d.w], 1);
        g_csrc[p0] = s.x; g_csrc[p1] = s.y; g_csrc[p2] = s.z; g_csrc[p3] = s.w;
    } else {
        for (int j = i; j < E; j++) {
            int p = atomicAdd(&g_pos[dst[j]], 1);
            g_csrc[p] = src[j];
        }
    }
}

// ------------- tensor-core GEMM: C[M x 128] = A @ W (+ el/er) --------------
// BM=128, BK=32, 8 warps; per warp 32(M) x 64(N); bf16x2 split, fp32 accum.
// ELR: epilogue computes el/er = per-head dot of C rows with alv/arv.

template <int K, bool ELR>
__launch_bounds__(256, 2)
__global__ void k_gemm_tc(const float* __restrict__ A,
                          const uint32_t* __restrict__ Whi,
                          const uint32_t* __restrict__ Wlo,
                          float* __restrict__ C, int M,
                          const float* __restrict__ alv,
                          const float* __restrict__ arv,
                          float* __restrict__ el, float* __restrict__ er) {
    __shared__ uint32_t sAhi[128 * 20], sAlo[128 * 20];
    __shared__ uint32_t sBhi[128 * 20], sBlo[128 * 20];
    __shared__ float sEl[512], sEr[512], sAl[128], sAr[128];
    const int t = threadIdx.x;
    const int rowBase = blockIdx.x * 128;
    const int wid = t >> 5, lane = t & 31;
    const int mwarp = wid >> 1, nwarp = wid & 1;
    const int g = lane >> 2, tig = lane & 3;
    const int NP = K >> 1;

    if (ELR && t < 128) { sAl[t] = alv[t]; sAr[t] = arv[t]; }

    float c[2][8][4];
    #pragma unroll
    for (int mi = 0; mi < 2; mi++)
        #pragma unroll
        for (int ni = 0; ni < 8; ni++)
            #pragma unroll
            for (int j = 0; j < 4; j++) c[mi][ni][j] = 0.f;

    for (int k0 = 0; k0 < K; k0 += 32) {
        const int kk0 = k0 >> 1;
        #pragma unroll
        for (int i = 0; i < 4; i++) {
            int idx = t + i * 256;
            int r = idx >> 3, c4 = idx & 7;
            int gr = rowBase + r;
            float4 v = make_float4(0.f, 0.f, 0.f, 0.f);
            if (gr < M) v = *(const float4*)(A + (size_t)gr * K + k0 + c4 * 4);
            uint32_t h0, l0, h1, l1;
            split2(v.x, v.y, h0, l0);
            split2(v.z, v.w, h1, l1);
            int b = r * 20 + c4 * 2;
            sAhi[b] = h0; sAlo[b] = l0;
            sAhi[b + 1] = h1; sAlo[b + 1] = l1;
        }
        #pragma unroll
        for (int i = 0; i < 2; i++) {
            int idx = t + i * 256;
            int nn = idx >> 2, j = (idx & 3) * 4;
            uint4 vh = *(const uint4*)(Whi + nn * NP + kk0 + j);
            uint4 vl = *(const uint4*)(Wlo + nn * NP + kk0 + j);
            int b = nn * 20 + j;
            sBhi[b] = vh.x; sBhi[b + 1] = vh.y; sBhi[b + 2] = vh.z; sBhi[b + 3] = vh.w;
            sBlo[b] = vl.x; sBlo[b + 1] = vl.y; sBlo[b + 2] = vl.z; sBlo[b + 3] = vl.w;
        }
        __syncthreads();

        #pragma unroll
        for (int ks = 0; ks < 2; ks++) {
            const int ko = ks * 8;
            uint32_t ah[2][4], al_[2][4];
            #pragma unroll
            for (int mi = 0; mi < 2; mi++) {
                int base = (mwarp * 32 + mi * 16 + g) * 20 + ko + tig;
                ah[mi][0] = sAhi[base];        al_[mi][0] = sAlo[base];
                ah[mi][1] = sAhi[base + 160];  al_[mi][1] = sAlo[base + 160];
                ah[mi][2] = sAhi[base + 4];    al_[mi][2] = sAlo[base + 4];
                ah[mi][3] = sAhi[base + 164];  al_[mi][3] = sAlo[base + 164];
            }
            #pragma unroll
            for (int ni = 0; ni < 8; ni++) {
                int bb = (nwarp * 64 + ni * 8 + g) * 20 + ko + tig;
                uint32_t bh0 = sBhi[bb], bh1 = sBhi[bb + 4];
                uint32_t bl0 = sBlo[bb], bl1 = sBlo[bb + 4];
                #pragma unroll
                for (int mi = 0; mi < 2; mi++) {
                    mma16816(c[mi][ni], ah[mi], bh0, bh1);
                    mma16816(c[mi][ni], ah[mi], bl0, bl1);
                    mma16816(c[mi][ni], al_[mi], bh0, bh1);
                }
            }
        }
        __syncthreads();
    }
    // store C
    #pragma unroll
    for (int mi = 0; mi < 2; mi++) {
        int r0 = rowBase + mwarp * 32 + mi * 16 + g;
        #pragma unroll
        for (int ni = 0; ni < 8; ni++) {
            int col = nwarp * 64 + ni * 8 + tig * 2;
            if (r0 < M)
                *(float2*)(C + (size_t)r0 * 128 + col) = make_float2(c[mi][ni][0], c[mi][ni][1]);
            if (r0 + 8 < M)
                *(float2*)(C + (size_t)(r0 + 8) * 128 + col) = make_float2(c[mi][ni][2], c[mi][ni][3]);
        }
    }
    // el/er epilogue
    if (ELR) {
        #pragma unroll
        for (int mi = 0; mi < 2; mi++) {
            float pel[2][2] = {{0.f, 0.f}, {0.f, 0.f}};
            float per_[2][2] = {{0.f, 0.f}, {0.f, 0.f}};
            #pragma unroll
            for (int ni = 0; ni < 8; ni++) {
                int col = nwarp * 64 + ni * 8 + tig * 2;
                int hh = ni >> 2;
                float a0 = sAl[col], a1 = sAl[col + 1];
                float r0 = sAr[col], r1 = sAr[col + 1];
                pel[0][hh] += c[mi][ni][0] * a0 + c[mi][ni][1] * a1;
                per_[0][hh] += c[mi][ni][0] * r0 + c[mi][ni][1] * r1;
                pel[1][hh] += c[mi][ni][2] * a0 + c[mi][ni][3] * a1;
                per_[1][hh] += c[mi][ni][2] * r0 + c[mi][ni][3] * r1;
            }
            #pragma unroll
            for (int gg = 0; gg < 2; gg++)
                #pragma unroll
                for (int hh = 0; hh < 2; hh++) {
                    float v = pel[gg][hh], w = per_[gg][hh];
                    v += __shfl_xor_sync(0xffffffffu, v, 1);
                    v += __shfl_xor_sync(0xffffffffu, v, 2);
                    w += __shfl_xor_sync(0xffffffffu, w, 1);
                    w += __shfl_xor_sync(0xffffffffu, w, 2);
                    if (tig == 0) {
                        int r = mwarp * 32 + mi * 16 + g + gg * 8;
                        sEl[r * 4 + nwarp * 2 + hh] = v;
                        sEr[r * 4 + nwarp * 2 + hh] = w;
                    }
                }
        }
        __syncthreads();
        #pragma unroll
        for (int i0 = 0; i0 < 2; i0++) {
            int i = t + i0 * 256;
            int gr = rowBase + (i >> 2);
            if (gr < M) {
                el[gr * 4 + (i & 3)] = sEl[i];
                er[gr * 4 + (i & 3)] = sEr[i];
            }
        }
    }
}

// -------------- warp-per-node aggregation, H=4 D=32, 1 pass ----------------
// lane owns dims [4*lane, 4*lane+3] (head = lane>>3). Lean: no fusion.

__launch_bounds__(256)
__global__ void k_agg4(const float4* __restrict__ feat4, const float* __restrict__ el,
                       const float* __restrict__ er, const float4* __restrict__ res4,
                       const float4* __restrict__ bias4, float4* __restrict__ out4,
                       int n) {
    int node = blockIdx.x * 8 + (threadIdx.x >> 5);
    if (node >= n) return;
    int lane = threadIdx.x & 31;
    int h = lane & 3, eo = lane >> 2, h4 = lane >> 3;
    int rs = g_off[node], re = g_off[node + 1];
    float er_h = er[node * 4 + h];

    float4 acc = make_float4(0.f, 0.f, 0.f, 0.f);
    float den = 0.f;
    for (int b = rs; b < re; b += 8) {
        int e = b + eo;
        int s = -1;
        float ee = 0.f;
        if (e < re) {
            s = g_csrc[e];
            float v = el[s * 4 + h] + er_h;
            v = v > 0.f ? v : 0.2f * v;
            ee = __expf(v);
            den += ee;
        }
        #pragma unroll
        for (int q = 0; q < 8; q++) {
            int   sq = __shfl_sync(0xffffffffu, s, q * 4);
            float eq = __shfl_sync(0xffffffffu, ee, q * 4 + h4);
            if (sq < 0) break;   // warp-uniform
            float4 f = feat4[(size_t)sq * 32 + lane];
            acc.x = fmaf(eq, f.x, acc.x);
            acc.y = fmaf(eq, f.y, acc.y);
            acc.z = fmaf(eq, f.z, acc.z);
            acc.w = fmaf(eq, f.w, acc.w);
        }
    }
    den += __shfl_xor_sync(0xffffffffu, den, 16);
    den += __shfl_xor_sync(0xffffffffu, den, 8);
    den += __shfl_xor_sync(0xffffffffu, den, 4);
    float inv = 1.f / __shfl_sync(0xffffffffu, den, h4);

    float4 o;
    o.x = acc.x * inv; o.y = acc.y * inv; o.z = acc.z * inv; o.w = acc.w * inv;
    if (res4) {
        float4 r = res4[(size_t)node * 32 + lane];
        o.x += r.x; o.y += r.y; o.z += r.z; o.w += r.w;
    }
    float4 bb = bias4[lane];
    o.x = fmaxf(o.x + bb.x, 0.f);   // both 4-head layers use relu
    o.y = fmaxf(o.y + bb.y, 0.f);
    o.z = fmaxf(o.z + bb.z, 0.f);
    o.w = fmaxf(o.w + bb.w, 0.f);
    out4[(size_t)node * 32 + lane] = o;
}

// ---------------------- layer 3: fused small GEMM --------------------------
// f3p (stride 8) = h@W3, er3p = f3*ar3, rbase = sum_j(h@resW3 + b3).

__global__ void k_l3gemm(const float* __restrict__ h, const float* __restrict__ W3,
                         const float* __restrict__ rW3, const float* __restrict__ ar3,
                         const float* __restrict__ b3, float* __restrict__ f3p,
                         float* __restrict__ er3p, float* __restrict__ rbase, int n) {
    __shared__ float sW[768], sR[768];
    int t = threadIdx.x;
    for (int i = t; i < 768; i += 256) { sW[i] = W3[i]; sR[i] = rW3[i]; }
    __syncthreads();
    int node = blockIdx.x * 256 + t;
    if (node >= n) return;
    const float4* hr = (const float4*)(h + (size_t)node * 128);
    float acc[6] = {0.f, 0.f, 0.f, 0.f, 0.f, 0.f};
    float rac[6] = {0.f, 0.f, 0.f, 0.f, 0.f, 0.f};
    #pragma unroll 8
    for (int k4 = 0; k4 < 32; k4++) {
        float4 a = hr[k4];
        int k = k4 * 4;
        #pragma unroll
        for (int j = 0; j < 6; j++) {
            acc[j] += a.x * sW[(k + 0) * 6 + j] + a.y * sW[(k + 1) * 6 + j]
                    + a.z * sW[(k + 2) * 6 + j] + a.w * sW[(k + 3) * 6 + j];
            rac[j] += a.x * sR[(k + 0) * 6 + j] + a.y * sR[(k + 1) * 6 + j]
                    + a.z * sR[(k + 2) * 6 + j] + a.w * sR[(k + 3) * 6 + j];
        }
    }
    float rb = 0.f;
    #pragma unroll
    for (int j = 0; j < 6; j++) {
        f3p [node * 8 + j] = acc[j];
        er3p[node * 8 + j] = acc[j] * ar3[j];
        rb += rac[j] + b3[j];
    }
    f3p [node * 8 + 6] = 0.f; f3p [node * 8 + 7] = 0.f;
    er3p[node * 8 + 6] = 0.f; er3p[node * 8 + 7] = 0.f;
    rbase[node] = rb;
}

// --------- layer 3 aggregation (H=6, D=1) + head mean, single pass ---------

__global__ void k_agg3(const float* __restrict__ f3p, const float* __restrict__ er3p,
                       const float* __restrict__ al3, const float* __restrict__ rbase,
                       float* __restrict__ out, int n) {
    int node = blockIdx.x * 8 + (threadIdx.x >> 5);
    if (node >= n) return;
    int lane = threadIdx.x & 31;
    int rs = g_off[node], re = g_off[node + 1];
    float al[6];
    #pragma unroll
    for (int j = 0; j < 6; j++) al[j] = al3[j];
    float4 e0 = *(const float4*)(er3p + (size_t)node * 8);
    float4 e1 = *(const float4*)(er3p + (size_t)node * 8 + 4);
    float erh[6] = {e0.x, e0.y, e0.z, e0.w, e1.x, e1.y};

    float acc[6], den[6];
    #pragma unroll
    for (int j = 0; j < 6; j++) { acc[j] = 0.f; den[j] = 0.f; }
    for (int e = rs + lane; e < re; e += 32) {
        int s = g_csrc[e];
        float4 f0 = *(const float4*)(f3p + (size_t)s * 8);
        float4 f1 = *(const float4*)(f3p + (size_t)s * 8 + 4);
        float f[6] = {f0.x, f0.y, f0.z, f0.w, f1.x, f1.y};
        #pragma unroll
        for (int j = 0; j < 6; j++) {
            float v = fmaf(f[j], al[j], erh[j]);
            v = v > 0.f ? v : 0.2f * v;
            float ee = __expf(v);
            den[j] += ee;
            acc[j] = fmaf(ee, f[j], acc[j]);
        }
    }
    #pragma unroll
    for (int j = 0; j < 6; j++) {
        #pragma unroll
        for (int o = 16; o > 0; o >>= 1) {
            acc[j] += __shfl_xor_sync(0xffffffffu, acc[j], o);
            den[j] += __shfl_xor_sync(0xffffffffu, den[j], o);
        }
    }
    if (lane == 0) {
        float o_ = 0.f;
        #pragma unroll
        for (int j = 0; j < 6; j++) o_ += acc[j] / den[j];
        out[node] = (o_ + rbase[node]) * (1.f / 6.f);
    }
}

// ------------------------------- launcher ----------------------------------

extern "C" void kernel_launch(void* const* d_in, const int* in_sizes, int n_in,
                              void* d_out, int out_size) {
    const float* x   = (const float*)d_in[0];
    const int*   src = (const int*)  d_in[1];
    const int*   dst = (const int*)  d_in[2];
    const float* W1  = (const float*)d_in[3];
    const float* al1 = (const float*)d_in[4];
    const float* ar1 = (const float*)d_in[5];
    const float* b1  = (const float*)d_in[6];
    const float* W2  = (const float*)d_in[7];
    const float* al2 = (const float*)d_in[8];
    const float* ar2 = (const float*)d_in[9];
    const float* b2  = (const float*)d_in[10];
    const float* rW2 = (const float*)d_in[11];
    const float* W3  = (const float*)d_in[12];
    const float* al3 = (const float*)d_in[13];
    const float* ar3 = (const float*)d_in[14];
    const float* b3  = (const float*)d_in[15];
    const float* rW3 = (const float*)d_in[16];
    int n = in_sizes[0] / 64;
    int E = in_sizes[1];
    float* out = (float*)d_out;

    float *feat, *res, *h1, *el, *er, *f3p, *er3p, *rb3;
    int *cnt, *bflag;
    uint32_t *w1hi, *w1lo, *w2hi, *w2lo, *r2hi, *r2lo;
    cudaGetSymbolAddress((void**)&feat, g_feat);
    cudaGetSymbolAddress((void**)&res,  g_res);
    cudaGetSymbolAddress((void**)&h1,   g_h1);
    cudaGetSymbolAddress((void**)&el,   g_el);
    cudaGetSymbolAddress((void**)&er,   g_er);
    cudaGetSymbolAddress((void**)&f3p,  g_f3p);
    cudaGetSymbolAddress((void**)&er3p, g_er3p);
    cudaGetSymbolAddress((void**)&rb3,  g_rb3);
    cudaGetSymbolAddress((void**)&cnt,  g_cnt);
    cudaGetSymbolAddress((void**)&bflag, g_bflag);
    cudaGetSymbolAddress((void**)&w1hi, g_w1hi);
    cudaGetSymbolAddress((void**)&w1lo, g_w1lo);
    cudaGetSymbolAddress((void**)&w2hi, g_w2hi);
    cudaGetSymbolAddress((void**)&w2lo, g_w2lo);
    cudaGetSymbolAddress((void**)&r2hi, g_r2hi);
    cudaGetSymbolAddress((void**)&r2lo, g_r2lo);

    // side stream + events, created once (host-side handles only)
    static cudaStream_t s2 = nullptr;
    static cudaEvent_t evFork = nullptr, evJoin = nullptr;
    if (!s2) {
        cudaStreamCreateWithFlags(&s2, cudaStreamNonBlocking);
        cudaEventCreateWithFlags(&evFork, cudaEventDisableTiming);
        cudaEventCreateWithFlags(&evJoin, cudaEventDisableTiming);
    }

    int nb = (n + 1023) / 1024;
    int gb = (n + 127) / 128;
    int ab = (n + 7) / 8;

    // --- fork: CSR build on s2, weight prep + GEMM1 on main stream ---
    cudaEventRecord(evFork, 0);
    cudaStreamWaitEvent(s2, evFork, 0);

    cudaMemsetAsync(cnt,   0, (size_t)n * sizeof(int), s2);
    cudaMemsetAsync(bflag, 0, 64 * sizeof(int), s2);
    k_hist   <<<(E + 1023) / 1024, 256, 0, s2>>>(dst, E);
    k_scan2  <<<nb, 1024, 0, s2>>>(n, E);
    k_scatter<<<(E + 1023) / 1024, 256, 0, s2>>>(src, dst, E);
    cudaEventRecord(evJoin, s2);

    k_prep<<<80, 256>>>(W1, W2, rW2);
    k_gemm_tc<64, true><<<gb, 256>>>(x, w1hi, w1lo, feat, n, al1, ar1, el, er);

    cudaStreamWaitEvent(0, evJoin, 0);

    // --- layer 1 aggregate -> h1 ---
    k_agg4<<<ab, 256>>>((const float4*)feat, el, er, (const float4*)nullptr,
                        (const float4*)b1, (float4*)h1, n);

    // --- layer 2: dual GEMMs (+el/er), aggregate -> h1 (reuse) ---
    k_gemm_tc<128, true ><<<gb, 256>>>(h1, w2hi, w2lo, feat, n, al2, ar2, el, er);
    k_gemm_tc<128, false><<<gb, 256>>>(h1, r2hi, r2lo, res, n, nullptr, nullptr,
                                       nullptr, nullptr);
    k_agg4<<<ab, 256>>>((const float4*)feat, el, er, (const float4*)res,
                        (const float4*)b2, (float4*)h1, n);

    // --- layer 3: projection + aggregation -> output ---
    k_l3gemm<<<(n + 255) / 256, 256>>>(h1, W3, rW3, ar3, b3, f3p, er3p, rb3, n);
    k_agg3<<<ab, 256>>>(f3p, er3p, al3, rb3, out, n);
}

// round 7
// speedup vs baseline: 1.3279x; 1.0715x over previous
#include <cuda_runtime.h>
#include <cuda_bf16.h>
#include <cuda_fp16.h>
#include <cstdint>

// ---------------------------------------------------------------------------
// GAT 3-layer pipeline on GB300 (sm_103a).  R5:
//  - feat stored/gathered as fp16 (halves dominant L2 traffic); attention
//    logits + softmax + accumulation stay fp32
//  - layer-2 dual-B GEMM: full split-A in dynamic smem, W2 and rW2 in one pass
//  - coalesced weight-split prep
//  - keeps: stream-forked CSR, lookback scan, GEMM+el/er fusion, bf16x2 MMA
// ---------------------------------------------------------------------------

#define MAXN 50176
#define MAXE 860160

__device__ int      g_cnt[MAXN];
__device__ int      g_off[MAXN + 1];
__device__ int      g_pos[MAXN];
__device__ int      g_bflag[64];
__device__ int      g_csrc[MAXE];
__device__ __half   g_featH[MAXN * 128];
__device__ float    g_res [MAXN * 128];
__device__ float    g_h1  [MAXN * 128];
__device__ float    g_el  [MAXN * 4];
__device__ float    g_er  [MAXN * 4];
__device__ float    g_f3p [MAXN * 8];
__device__ float    g_er3p[MAXN * 8];
__device__ float    g_rb3 [MAXN];
__device__ uint32_t g_w1hi[128 * 32], g_w1lo[128 * 32];    // K=64  -> 32 pairs
__device__ uint32_t g_w2hi[128 * 64], g_w2lo[128 * 64];    // K=128 -> 64 pairs
__device__ uint32_t g_r2hi[128 * 64], g_r2lo[128 * 64];

// --------------------------- bf16 split helpers ----------------------------

__device__ __forceinline__ void split2(float x, float y, uint32_t& h, uint32_t& l) {
    __nv_bfloat162 hh = __floats2bfloat162_rn(x, y);          // low 16 = x
    float hx = __bfloat162float(hh.x), hy = __bfloat162float(hh.y);
    __nv_bfloat162 ll = __floats2bfloat162_rn(x - hx, y - hy);
    h = *reinterpret_cast<uint32_t*>(&hh);
    l = *reinterpret_cast<uint32_t*>(&ll);
}

__device__ __forceinline__ void mma16816(float* c, const uint32_t* a,
                                         uint32_t b0, uint32_t b1) {
    asm volatile(
        "mma.sync.aligned.m16n8k16.row.col.f32.bf16.bf16.f32 "
        "{%0,%1,%2,%3}, {%4,%5,%6,%7}, {%8,%9}, {%0,%1,%2,%3};\n"
        : "+f"(c[0]), "+f"(c[1]), "+f"(c[2]), "+f"(c[3])
        : "r"(a[0]), "r"(a[1]), "r"(a[2]), "r"(a[3]), "r"(b0), "r"(b1));
}

// weight split, coalesced reads: consecutive threads take consecutive nn.
__global__ void k_prep(const float* __restrict__ W1, const float* __restrict__ W2,
                       const float* __restrict__ rW2) {
    int idx = blockIdx.x * 256 + threadIdx.x;
    const float* W;
    uint32_t *H, *L;
    int NP, local;
    if (idx < 4096)       { W = W1;  H = g_w1hi; L = g_w1lo; NP = 32; local = idx; }
    else if (idx < 12288) { W = W2;  H = g_w2hi; L = g_w2lo; NP = 64; local = idx - 4096; }
    else if (idx < 20480) { W = rW2; H = g_r2hi; L = g_r2lo; NP = 64; local = idx - 12288; }
    else return;
    int kk = local >> 7, nn = local & 127;
    float w0 = W[(2 * kk) * 128 + nn];
    float w1 = W[(2 * kk + 1) * 128 + nn];
    uint32_t h, l;
    split2(w0, w1, h, l);
    H[nn * NP + kk] = h;
    L[nn * NP + kk] = l;
}

// ------------------------------ CSR build ---------------------------------

__global__ void k_hist(const int* __restrict__ dst, int E) {
    int i = (blockIdx.x * blockDim.x + threadIdx.x) * 4;
    if (i + 3 < E) {
        int4 d = *(const int4*)(dst + i);
        atomicAdd(&g_cnt[d.x], 1);
        atomicAdd(&g_cnt[d.y], 1);
        atomicAdd(&g_cnt[d.z], 1);
        atomicAdd(&g_cnt[d.w], 1);
    } else {
        for (int j = i; j < E; j++) atomicAdd(&g_cnt[dst[j]], 1);
    }
}

// single-pass exclusive scan with lookback (all blocks resident).
__global__ void k_scan2(int n, int E) {
    __shared__ int ws[32];
    __shared__ int pre_s;
    int t = threadIdx.x, lane = t & 31, wid = t >> 5, b = blockIdx.x;
    int i = b * 1024 + t;
    int v = (i < n) ? g_cnt[i] : 0;
    int x = v;
    #pragma unroll
    for (int d = 1; d < 32; d <<= 1) {
        int y = __shfl_up_sync(0xffffffffu, x, d);
        if (lane >= d) x += y;
    }
    if (lane == 31) ws[wid] = x;
    __syncthreads();
    if (wid == 0) {
        int s = ws[lane];
        #pragma unroll
        for (int d = 1; d < 32; d <<= 1) {
            int y = __shfl_up_sync(0xffffffffu, s, d);
            if (lane >= d) s += y;
        }
        ws[lane] = s;
    }
    __syncthreads();
    int incl = x + (wid > 0 ? ws[wid - 1] : 0);
    if (t == 1023) atomicExch(&g_bflag[b], incl + 1);
    if (wid == 0) {
        int s = 0;
        for (int j = lane; j < b; j += 32) {
            int f;
            while ((f = atomicAdd(&g_bflag[j], 0)) == 0) { }
            s += f - 1;
        }
        #pragma unroll
        for (int o = 16; o > 0; o >>= 1) s += __shfl_xor_sync(0xffffffffu, s, o);
        if (lane == 0) pre_s = s;
    }
    __syncthreads();
    if (i < n) {
        int o = incl - v + pre_s;
        g_off[i] = o;
        g_pos[i] = o;
    }
    if (b == 0 && t == 0) g_off[n] = E;
}

__global__ void k_scatter(const int* __restrict__ src, const int* __restrict__ dst, int E) {
    int i = (blockIdx.x * blockDim.x + threadIdx.x) * 4;
    if (i + 3 < E) {
        int4 s = *(const int4*)(src + i);
        int4 d = *(const int4*)(dst + i);
        int p0 = atomicAdd(&g_pos[d.x], 1);
        int p1 = atomicAdd(&g_pos[d.y], 1);
        int p2 = atomicAdd(&g_pos[d.z], 1);
        int p3 = atomicAdd(&g_pos[d.w], 1);
        g_csrc[p0] = s.x; g_csrc[p1] = s.y; g_csrc[p2] = s.z; g_csrc[p3] = s.w;
    } else {
        for (int j = i; j < E; j++) {
            int p = atomicAdd(&g_pos[dst[j]], 1);
            g_csrc[p] = src[j];
        }
    }
}

// ---------------- layer-1 GEMM: featH[M x 128] = x @ W1 + el/er ------------
// BM=128, BK=32, 8 warps; per warp 32(M) x 64(N); bf16x2 split, fp32 accum.

__launch_bounds__(256, 2)
__global__ void k_gemm1(const float* __restrict__ A,
                        const uint32_t* __restrict__ Whi,
                        const uint32_t* __restrict__ Wlo,
                        __half* __restrict__ featH, int M,
                        const float* __restrict__ alv,
                        const float* __restrict__ arv,
                        float* __restrict__ el, float* __restrict__ er) {
    const int K = 64, NP = 32;
    __shared__ uint32_t sAhi[128 * 20], sAlo[128 * 20];
    __shared__ uint32_t sBhi[128 * 20], sBlo[128 * 20];
    __shared__ float sEl[512], sEr[512], sAl[128], sAr[128];
    const int t = threadIdx.x;
    const int rowBase = blockIdx.x * 128;
    const int wid = t >> 5, lane = t & 31;
    const int mwarp = wid >> 1, nwarp = wid & 1;
    const int g = lane >> 2, tig = lane & 3;

    if (t < 128) { sAl[t] = alv[t]; sAr[t] = arv[t]; }

    float c[2][8][4];
    #pragma unroll
    for (int mi = 0; mi < 2; mi++)
        #pragma unroll
        for (int ni = 0; ni < 8; ni++)
            #pragma unroll
            for (int j = 0; j < 4; j++) c[mi][ni][j] = 0.f;

    for (int k0 = 0; k0 < K; k0 += 32) {
        const int kk0 = k0 >> 1;
        #pragma unroll
        for (int i = 0; i < 4; i++) {
            int idx = t + i * 256;
            int r = idx >> 3, c4 = idx & 7;
            int gr = rowBase + r;
            float4 v = make_float4(0.f, 0.f, 0.f, 0.f);
            if (gr < M) v = *(const float4*)(A + (size_t)gr * K + k0 + c4 * 4);
            uint32_t h0, l0, h1, l1;
            split2(v.x, v.y, h0, l0);
            split2(v.z, v.w, h1, l1);
            int b = r * 20 + c4 * 2;
            sAhi[b] = h0; sAlo[b] = l0;
            sAhi[b + 1] = h1; sAlo[b + 1] = l1;
        }
        #pragma unroll
        for (int i = 0; i < 2; i++) {
            int idx = t + i * 256;
            int nn = idx >> 2, j = (idx & 3) * 4;
            uint4 vh = *(const uint4*)(Whi + nn * NP + kk0 + j);
            uint4 vl = *(const uint4*)(Wlo + nn * NP + kk0 + j);
            int b = nn * 20 + j;
            sBhi[b] = vh.x; sBhi[b + 1] = vh.y; sBhi[b + 2] = vh.z; sBhi[b + 3] = vh.w;
            sBlo[b] = vl.x; sBlo[b + 1] = vl.y; sBlo[b + 2] = vl.z; sBlo[b + 3] = vl.w;
        }
        __syncthreads();
        #pragma unroll
        for (int ks = 0; ks < 2; ks++) {
            const int ko = ks * 8;
            uint32_t ah[2][4], al_[2][4];
            #pragma unroll
            for (int mi = 0; mi < 2; mi++) {
                int base = (mwarp * 32 + mi * 16 + g) * 20 + ko + tig;
                ah[mi][0] = sAhi[base];        al_[mi][0] = sAlo[base];
                ah[mi][1] = sAhi[base + 160];  al_[mi][1] = sAlo[base + 160];
                ah[mi][2] = sAhi[base + 4];    al_[mi][2] = sAlo[base + 4];
                ah[mi][3] = sAhi[base + 164];  al_[mi][3] = sAlo[base + 164];
            }
            #pragma unroll
            for (int ni = 0; ni < 8; ni++) {
                int bb = (nwarp * 64 + ni * 8 + g) * 20 + ko + tig;
                uint32_t bh0 = sBhi[bb], bh1 = sBhi[bb + 4];
                uint32_t bl0 = sBlo[bb], bl1 = sBlo[bb + 4];
                #pragma unroll
                for (int mi = 0; mi < 2; mi++) {
                    mma16816(c[mi][ni], ah[mi], bh0, bh1);
                    mma16816(c[mi][ni], ah[mi], bl0, bl1);
                    mma16816(c[mi][ni], al_[mi], bh0, bh1);
                }
            }
        }
        __syncthreads();
    }
    // store feat as half
    #pragma unroll
    for (int mi = 0; mi < 2; mi++) {
        int r0 = rowBase + mwarp * 32 + mi * 16 + g;
        #pragma unroll
        for (int ni = 0; ni < 8; ni++) {
            int col = nwarp * 64 + ni * 8 + tig * 2;
            if (r0 < M)
                *(__half2*)(featH + (size_t)r0 * 128 + col) =
                    __floats2half2_rn(c[mi][ni][0], c[mi][ni][1]);
            if (r0 + 8 < M)
                *(__half2*)(featH + (size_t)(r0 + 8) * 128 + col) =
                    __floats2half2_rn(c[mi][ni][2], c[mi][ni][3]);
        }
    }
    // el/er epilogue (fp32)
    #pragma unroll
    for (int mi = 0; mi < 2; mi++) {
        float pel[2][2] = {{0.f, 0.f}, {0.f, 0.f}};
        float per_[2][2] = {{0.f, 0.f}, {0.f, 0.f}};
        #pragma unroll
        for (int ni = 0; ni < 8; ni++) {
            int col = nwarp * 64 + ni * 8 + tig * 2;
            int hh = ni >> 2;
            float a0 = sAl[col], a1 = sAl[col + 1];
            float r0 = sAr[col], r1 = sAr[col + 1];
            pel[0][hh] += c[mi][ni][0] * a0 + c[mi][ni][1] * a1;
            per_[0][hh] += c[mi][ni][0] * r0 + c[mi][ni][1] * r1;
            pel[1][hh] += c[mi][ni][2] * a0 + c[mi][ni][3] * a1;
            per_[1][hh] += c[mi][ni][2] * r0 + c[mi][ni][3] * r1;
        }
        #pragma unroll
        for (int gg = 0; gg < 2; gg++)
            #pragma unroll
            for (int hh = 0; hh < 2; hh++) {
                float v = pel[gg][hh], w = per_[gg][hh];
                v += __shfl_xor_sync(0xffffffffu, v, 1);
                v += __shfl_xor_sync(0xffffffffu, v, 2);
                w += __shfl_xor_sync(0xffffffffu, w, 1);
                w += __shfl_xor_sync(0xffffffffu, w, 2);
                if (tig == 0) {
                    int r = mwarp * 32 + mi * 16 + g + gg * 8;
                    sEl[r * 4 + nwarp * 2 + hh] = v;
                    sEr[r * 4 + nwarp * 2 + hh] = w;
                }
            }
    }
    __syncthreads();
    #pragma unroll
    for (int i0 = 0; i0 < 2; i0++) {
        int i = t + i0 * 256;
        int gr = rowBase + (i >> 2);
        if (gr < M) {
            el[gr * 4 + (i & 3)] = sEl[i];
            er[gr * 4 + (i & 3)] = sEr[i];
        }
    }
}

// --------- layer-2 dual GEMM: featH = h1@W2 (+el/er), res = h1@rW2 ---------
// Full split-A (128 x 128) resident in dynamic smem; B tiles streamed.

#define ASTRIDE 68

__launch_bounds__(256, 2)
__global__ void k_gemm2dual(const float* __restrict__ A,
                            const uint32_t* __restrict__ w2hi,
                            const uint32_t* __restrict__ w2lo,
                            const uint32_t* __restrict__ r2hi,
                            const uint32_t* __restrict__ r2lo,
                            __half* __restrict__ featH, float* __restrict__ res,
                            int M,
                            const float* __restrict__ alv,
                            const float* __restrict__ arv,
                            float* __restrict__ el, float* __restrict__ er) {
    extern __shared__ uint32_t sm[];
    uint32_t* sAhi = sm;                        // 128*ASTRIDE
    uint32_t* sAlo = sAhi + 128 * ASTRIDE;
    uint32_t* sBhi = sAlo + 128 * ASTRIDE;      // 128*20
    uint32_t* sBlo = sBhi + 128 * 20;
    float* sEl = (float*)(sBlo + 128 * 20);     // 512
    float* sEr = sEl + 512;
    float* sAl = sEr + 512;                     // 128
    float* sAr = sAl + 128;

    const int t = threadIdx.x;
    const int rowBase = blockIdx.x * 128;
    const int wid = t >> 5, lane = t & 31;
    const int mwarp = wid >> 1, nwarp = wid & 1;
    const int g = lane >> 2, tig = lane & 3;

    if (t < 128) { sAl[t] = alv[t]; sAr[t] = arv[t]; }

    // load + split full A tile: 128 rows x 128 k = 4096 float4
    #pragma unroll
    for (int i = 0; i < 16; i++) {
        int idx = t + i * 256;
        int r = idx >> 5, c4 = idx & 31;
        int gr = rowBase + r;
        float4 v = make_float4(0.f, 0.f, 0.f, 0.f);
        if (gr < M) v = *(const float4*)(A + (size_t)gr * 128 + c4 * 4);
        uint32_t h0, l0, h1, l1;
        split2(v.x, v.y, h0, l0);
        split2(v.z, v.w, h1, l1);
        int b = r * ASTRIDE + c4 * 2;
        sAhi[b] = h0; sAlo[b] = l0;
        sAhi[b + 1] = h1; sAlo[b + 1] = l1;
    }

    #pragma unroll
    for (int bmat = 0; bmat < 2; bmat++) {
        const uint32_t* Whi = bmat ? r2hi : w2hi;
        const uint32_t* Wlo = bmat ? r2lo : w2lo;
        float c[2][8][4];
        #pragma unroll
        for (int mi = 0; mi < 2; mi++)
            #pragma unroll
            for (int ni = 0; ni < 8; ni++)
                #pragma unroll
                for (int j = 0; j < 4; j++) c[mi][ni][j] = 0.f;

        for (int kt = 0; kt < 4; kt++) {
            __syncthreads();      // protect sB (and A on first pass)
            #pragma unroll
            for (int i = 0; i < 2; i++) {
                int idx = t + i * 256;
                int nn = idx >> 2, j = (idx & 3) * 4;
                uint4 vh = *(const uint4*)(Whi + nn * 64 + kt * 16 + j);
                uint4 vl = *(const uint4*)(Wlo + nn * 64 + kt * 16 + j);
                int b = nn * 20 + j;
                sBhi[b] = vh.x; sBhi[b + 1] = vh.y; sBhi[b + 2] = vh.z; sBhi[b + 3] = vh.w;
                sBlo[b] = vl.x; sBlo[b + 1] = vl.y; sBlo[b + 2] = vl.z; sBlo[b + 3] = vl.w;
            }
            __syncthreads();
            #pragma unroll
            for (int ks = 0; ks < 2; ks++) {
                const int ko = ks * 8;
                uint32_t ah[2][4], al_[2][4];
                #pragma unroll
                for (int mi = 0; mi < 2; mi++) {
                    int base = (mwarp * 32 + mi * 16 + g) * ASTRIDE + kt * 16 + ko + tig;
                    ah[mi][0] = sAhi[base];                 al_[mi][0] = sAlo[base];
                    ah[mi][1] = sAhi[base + 8 * ASTRIDE];   al_[mi][1] = sAlo[base + 8 * ASTRIDE];
                    ah[mi][2] = sAhi[base + 4];             al_[mi][2] = sAlo[base + 4];
                    ah[mi][3] = sAhi[base + 8 * ASTRIDE + 4]; al_[mi][3] = sAlo[base + 8 * ASTRIDE + 4];
                }
                #pragma unroll
                for (int ni = 0; ni < 8; ni++) {
                    int bb = (nwarp * 64 + ni * 8 + g) * 20 + ko + tig;
                    uint32_t bh0 = sBhi[bb], bh1 = sBhi[bb + 4];
                    uint32_t bl0 = sBlo[bb], bl1 = sBlo[bb + 4];
                    #pragma unroll
                    for (int mi = 0; mi < 2; mi++) {
                        mma16816(c[mi][ni], ah[mi], bh0, bh1);
                        mma16816(c[mi][ni], ah[mi], bl0, bl1);
                        mma16816(c[mi][ni], al_[mi], bh0, bh1);
                    }
                }
            }
        }

        if (bmat == 0) {
            // feat as half + el/er
            #pragma unroll
            for (int mi = 0; mi < 2; mi++) {
                int r0 = rowBase + mwarp * 32 + mi * 16 + g;
                #pragma unroll
                for (int ni = 0; ni < 8; ni++) {
                    int col = nwarp * 64 + ni * 8 + tig * 2;
                    if (r0 < M)
                        *(__half2*)(featH + (size_t)r0 * 128 + col) =
                            __floats2half2_rn(c[mi][ni][0], c[mi][ni][1]);
                    if (r0 + 8 < M)
                        *(__half2*)(featH + (size_t)(r0 + 8) * 128 + col) =
                            __floats2half2_rn(c[mi][ni][2], c[mi][ni][3]);
                }
            }
            #pragma unroll
            for (int mi = 0; mi < 2; mi++) {
                float pel[2][2] = {{0.f, 0.f}, {0.f, 0.f}};
                float per_[2][2] = {{0.f, 0.f}, {0.f, 0.f}};
                #pragma unroll
                for (int ni = 0; ni < 8; ni++) {
                    int col = nwarp * 64 + ni * 8 + tig * 2;
                    int hh = ni >> 2;
                    float a0 = sAl[col], a1 = sAl[col + 1];
                    float r0 = sAr[col], r1 = sAr[col + 1];
                    pel[0][hh] += c[mi][ni][0] * a0 + c[mi][ni][1] * a1;
                    per_[0][hh] += c[mi][ni][0] * r0 + c[mi][ni][1] * r1;
                    pel[1][hh] += c[mi][ni][2] * a0 + c[mi][ni][3] * a1;
                    per_[1][hh] += c[mi][ni][2] * r0 + c[mi][ni][3] * r1;
                }
                #pragma unroll
                for (int gg = 0; gg < 2; gg++)
                    #pragma unroll
                    for (int hh = 0; hh < 2; hh++) {
                        float v = pel[gg][hh], w = per_[gg][hh];
                        v += __shfl_xor_sync(0xffffffffu, v, 1);
                        v += __shfl_xor_sync(0xffffffffu, v, 2);
                        w += __shfl_xor_sync(0xffffffffu, w, 1);
                        w += __shfl_xor_sync(0xffffffffu, w, 2);
                        if (tig == 0) {
                            int r = mwarp * 32 + mi * 16 + g + gg * 8;
                            sEl[r * 4 + nwarp * 2 + hh] = v;
                            sEr[r * 4 + nwarp * 2 + hh] = w;
                        }
                    }
            }
            __syncthreads();
            #pragma unroll
            for (int i0 = 0; i0 < 2; i0++) {
                int i = t + i0 * 256;
                int gr = rowBase + (i >> 2);
                if (gr < M) {
                    el[gr * 4 + (i & 3)] = sEl[i];
                    er[gr * 4 + (i & 3)] = sEr[i];
                }
            }
        } else {
            // residual, fp32
            #pragma unroll
            for (int mi = 0; mi < 2; mi++) {
                int r0 = rowBase + mwarp * 32 + mi * 16 + g;
                #pragma unroll
                for (int ni = 0; ni < 8; ni++) {
                    int col = nwarp * 64 + ni * 8 + tig * 2;
                    if (r0 < M)
                        *(float2*)(res + (size_t)r0 * 128 + col) =
                            make_float2(c[mi][ni][0], c[mi][ni][1]);
                    if (r0 + 8 < M)
                        *(float2*)(res + (size_t)(r0 + 8) * 128 + col) =
                            make_float2(c[mi][ni][2], c[mi][ni][3]);
                }
            }
        }
    }
}

// -------------- warp-per-node aggregation, H=4 D=32, 1 pass ----------------
// lane owns dims [4*lane, 4*lane+3] (head = lane>>3); feat gathered as fp16.

__launch_bounds__(256)
__global__ void k_agg4(const uint2* __restrict__ featH2, const float* __restrict__ el,
                       const float* __restrict__ er, const float4* __restrict__ res4,
                       const float4* __restrict__ bias4, float4* __restrict__ out4,
                       int n) {
    int node = blockIdx.x * 8 + (threadIdx.x >> 5);
    if (node >= n) return;
    int lane = threadIdx.x & 31;
    int h = lane & 3, eo = lane >> 2, h4 = lane >> 3;
    int rs = g_off[node], re = g_off[node + 1];
    float er_h = er[node * 4 + h];

    float4 acc = make_float4(0.f, 0.f, 0.f, 0.f);
    float den = 0.f;
    for (int b = rs; b < re; b += 8) {
        int e = b + eo;
        int s = -1;
        float ee = 0.f;
        if (e < re) {
            s = g_csrc[e];
            float v = el[s * 4 + h] + er_h;
            v = v > 0.f ? v : 0.2f * v;
            ee = __expf(v);
            den += ee;
        }
        #pragma unroll
        for (int q = 0; q < 8; q++) {
            int   sq = __shfl_sync(0xffffffffu, s, q * 4);
            float eq = __shfl_sync(0xffffffffu, ee, q * 4 + h4);
            if (sq < 0) break;   // warp-uniform
            uint2 u = featH2[(size_t)sq * 32 + lane];
            float2 f01 = __half22float2(*reinterpret_cast<__half2*>(&u.x));
            float2 f23 = __half22float2(*reinterpret_cast<__half2*>(&u.y));
            acc.x = fmaf(eq, f01.x, acc.x);
            acc.y = fmaf(eq, f01.y, acc.y);
            acc.z = fmaf(eq, f23.x, acc.z);
            acc.w = fmaf(eq, f23.y, acc.w);
        }
    }
    den += __shfl_xor_sync(0xffffffffu, den, 16);
    den += __shfl_xor_sync(0xffffffffu, den, 8);
    den += __shfl_xor_sync(0xffffffffu, den, 4);
    float inv = 1.f / __shfl_sync(0xffffffffu, den, h4);

    float4 o;
    o.x = acc.x * inv; o.y = acc.y * inv; o.z = acc.z * inv; o.w = acc.w * inv;
    if (res4) {
        float4 r = res4[(size_t)node * 32 + lane];
        o.x += r.x; o.y += r.y; o.z += r.z; o.w += r.w;
    }
    float4 bb = bias4[lane];
    o.x = fmaxf(o.x + bb.x, 0.f);   // both 4-head layers use relu
    o.y = fmaxf(o.y + bb.y, 0.f);
    o.z = fmaxf(o.z + bb.z, 0.f);
    o.w = fmaxf(o.w + bb.w, 0.f);
    out4[(size_t)node * 32 + lane] = o;
}

// ---------------------- layer 3: fused small GEMM --------------------------

__global__ void k_l3gemm(const float* __restrict__ h, const float* __restrict__ W3,
                         const float* __restrict__ rW3, const float* __restrict__ ar3,
                         const float* __restrict__ b3, float* __restrict__ f3p,
                         float* __restrict__ er3p, float* __restrict__ rbase, int n) {
    __shared__ float sW[768], sR[768];
    int t = threadIdx.x;
    for (int i = t; i < 768; i += 256) { sW[i] = W3[i]; sR[i] = rW3[i]; }
    __syncthreads();
    int node = blockIdx.x * 256 + t;
    if (node >= n) return;
    const float4* hr = (const float4*)(h + (size_t)node * 128);
    float acc[6] = {0.f, 0.f, 0.f, 0.f, 0.f, 0.f};
    float rac[6] = {0.f, 0.f, 0.f, 0.f, 0.f, 0.f};
    #pragma unroll 8
    for (int k4 = 0; k4 < 32; k4++) {
        float4 a = hr[k4];
        int k = k4 * 4;
        #pragma unroll
        for (int j = 0; j < 6; j++) {
            acc[j] += a.x * sW[(k + 0) * 6 + j] + a.y * sW[(k + 1) * 6 + j]
                    + a.z * sW[(k + 2) * 6 + j] + a.w * sW[(k + 3) * 6 + j];
            rac[j] += a.x * sR[(k + 0) * 6 + j] + a.y * sR[(k + 1) * 6 + j]
                    + a.z * sR[(k + 2) * 6 + j] + a.w * sR[(k + 3) * 6 + j];
        }
    }
    float rb = 0.f;
    #pragma unroll
    for (int j = 0; j < 6; j++) {
        f3p [node * 8 + j] = acc[j];
        er3p[node * 8 + j] = acc[j] * ar3[j];
        rb += rac[j] + b3[j];
    }
    f3p [node * 8 + 6] = 0.f; f3p [node * 8 + 7] = 0.f;
    er3p[node * 8 + 6] = 0.f; er3p[node * 8 + 7] = 0.f;
    rbase[node] = rb;
}

// --------- layer 3 aggregation (H=6, D=1) + head mean, single pass ---------

__global__ void k_agg3(const float* __restrict__ f3p, const float* __restrict__ er3p,
                       const float* __restrict__ al3, const float* __restrict__ rbase,
                       float* __restrict__ out, int n) {
    int node = blockIdx.x * 8 + (threadIdx.x >> 5);
    if (node >= n) return;
    int lane = threadIdx.x & 31;
    int rs = g_off[node], re = g_off[node + 1];
    float al[6];
    #pragma unroll
    for (int j = 0; j < 6; j++) al[j] = al3[j];
    float4 e0 = *(const float4*)(er3p + (size_t)node * 8);
    float4 e1 = *(const float4*)(er3p + (size_t)node * 8 + 4);
    float erh[6] = {e0.x, e0.y, e0.z, e0.w, e1.x, e1.y};

    float acc[6], den[6];
    #pragma unroll
    for (int j = 0; j < 6; j++) { acc[j] = 0.f; den[j] = 0.f; }
    for (int e = rs + lane; e < re; e += 32) {
        int s = g_csrc[e];
        float4 f0 = *(const float4*)(f3p + (size_t)s * 8);
        float4 f1 = *(const float4*)(f3p + (size_t)s * 8 + 4);
        float f[6] = {f0.x, f0.y, f0.z, f0.w, f1.x, f1.y};
        #pragma unroll
        for (int j = 0; j < 6; j++) {
            float v = fmaf(f[j], al[j], erh[j]);
            v = v > 0.f ? v : 0.2f * v;
            float ee = __expf(v);
            den[j] += ee;
            acc[j] = fmaf(ee, f[j], acc[j]);
        }
    }
    #pragma unroll
    for (int j = 0; j < 6; j++) {
        #pragma unroll
        for (int o = 16; o > 0; o >>= 1) {
            acc[j] += __shfl_xor_sync(0xffffffffu, acc[j], o);
            den[j] += __shfl_xor_sync(0xffffffffu, den[j], o);
        }
    }
    if (lane == 0) {
        float o_ = 0.f;
        #pragma unroll
        for (int j = 0; j < 6; j++) o_ += acc[j] / den[j];
        out[node] = (o_ + rbase[node]) * (1.f / 6.f);
    }
}

// ------------------------------- launcher ----------------------------------

#define G2_SMEM ((128 * ASTRIDE * 2 + 128 * 20 * 2) * 4 + (512 * 2 + 128 * 2) * 4)

extern "C" void kernel_launch(void* const* d_in, const int* in_sizes, int n_in,
                              void* d_out, int out_size) {
    const float* x   = (const float*)d_in[0];
    const int*   src = (const int*)  d_in[1];
    const int*   dst = (const int*)  d_in[2];
    const float* W1  = (const float*)d_in[3];
    const float* al1 = (const float*)d_in[4];
    const float* ar1 = (const float*)d_in[5];
    const float* b1  = (const float*)d_in[6];
    const float* W2  = (const float*)d_in[7];
    const float* al2 = (const float*)d_in[8];
    const float* ar2 = (const float*)d_in[9];
    const float* b2  = (const float*)d_in[10];
    const float* rW2 = (const float*)d_in[11];
    const float* W3  = (const float*)d_in[12];
    const float* al3 = (const float*)d_in[13];
    const float* ar3 = (const float*)d_in[14];
    const float* b3  = (const float*)d_in[15];
    const float* rW3 = (const float*)d_in[16];
    int n = in_sizes[0] / 64;
    int E = in_sizes[1];
    float* out = (float*)d_out;

    float *res, *h1, *el, *er, *f3p, *er3p, *rb3;
    __half* featH;
    int *cnt, *bflag;
    uint32_t *w1hi, *w1lo, *w2hi, *w2lo, *r2hi, *r2lo;
    cudaGetSymbolAddress((void**)&featH, g_featH);
    cudaGetSymbolAddress((void**)&res,  g_res);
    cudaGetSymbolAddress((void**)&h1,   g_h1);
    cudaGetSymbolAddress((void**)&el,   g_el);
    cudaGetSymbolAddress((void**)&er,   g_er);
    cudaGetSymbolAddress((void**)&f3p,  g_f3p);
    cudaGetSymbolAddress((void**)&er3p, g_er3p);
    cudaGetSymbolAddress((void**)&rb3,  g_rb3);
    cudaGetSymbolAddress((void**)&cnt,  g_cnt);
    cudaGetSymbolAddress((void**)&bflag, g_bflag);
    cudaGetSymbolAddress((void**)&w1hi, g_w1hi);
    cudaGetSymbolAddress((void**)&w1lo, g_w1lo);
    cudaGetSymbolAddress((void**)&w2hi, g_w2hi);
    cudaGetSymbolAddress((void**)&w2lo, g_w2lo);
    cudaGetSymbolAddress((void**)&r2hi, g_r2hi);
    cudaGetSymbolAddress((void**)&r2lo, g_r2lo);

    static cudaStream_t s2 = nullptr;
    static cudaEvent_t evFork = nullptr, evJoin = nullptr;
    if (!s2) {
        cudaStreamCreateWithFlags(&s2, cudaStreamNonBlocking);
        cudaEventCreateWithFlags(&evFork, cudaEventDisableTiming);
        cudaEventCreateWithFlags(&evJoin, cudaEventDisableTiming);
        cudaFuncSetAttribute(k_gemm2dual,
                             cudaFuncAttributeMaxDynamicSharedMemorySize, G2_SMEM);
    }

    int nb = (n + 1023) / 1024;
    int gb = (n + 127) / 128;
    int ab = (n + 7) / 8;

    // --- fork: CSR build on s2, weight prep + GEMM1 on main stream ---
    cudaEventRecord(evFork, 0);
    cudaStreamWaitEvent(s2, evFork, 0);

    cudaMemsetAsync(cnt,   0, (size_t)n * sizeof(int), s2);
    cudaMemsetAsync(bflag, 0, 64 * sizeof(int), s2);
    k_hist   <<<(E + 1023) / 1024, 256, 0, s2>>>(dst, E);
    k_scan2  <<<nb, 1024, 0, s2>>>(n, E);
    k_scatter<<<(E + 1023) / 1024, 256, 0, s2>>>(src, dst, E);
    cudaEventRecord(evJoin, s2);

    k_prep<<<80, 256>>>(W1, W2, rW2);
    k_gemm1<<<gb, 256>>>(x, w1hi, w1lo, featH, n, al1, ar1, el, er);

    cudaStreamWaitEvent(0, evJoin, 0);

    // --- layer 1 aggregate -> h1 (fp32) ---
    k_agg4<<<ab, 256>>>((const uint2*)featH, el, er, (const float4*)nullptr,
                        (const float4*)b1, (float4*)h1, n);

    // --- layer 2: dual GEMM (+el/er), aggregate -> h1 (reuse) ---
    k_gemm2dual<<<gb, 256, G2_SMEM>>>(h1, w2hi, w2lo, r2hi, r2lo,
                                      featH, res, n, al2, ar2, el, er);
    k_agg4<<<ab, 256>>>((const uint2*)featH, el, er, (const float4*)res,
                        (const float4*)b2, (float4*)h1, n);

    // --- layer 3: projection + aggregation -> output ---
    k_l3gemm<<<(n + 255) / 256, 256>>>(h1, W3, rW3, ar3, b3, f3p, er3p, rb3, n);
    k_agg3<<<ab, 256>>>(f3p, er3p, al3, rb3, out, n);
}

// round 8
// speedup vs baseline: 1.3393x; 1.0086x over previous
#include <cuda_runtime.h>
#include <cuda_bf16.h>
#include <cuda_fp16.h>
#include <cstdint>

// ---------------------------------------------------------------------------
// GAT 3-layer pipeline on GB300 (sm_103a).  R6:
//  - agg4: 16-lane-per-edge LDG.128 gather (2 edges/iter), split hot/fringe
//  - h1 stored pre-split bf16 hi/lo by agg4-L1 -> gemm2dual A load is a copy
//  - prepW2 overlapped on 3rd stream; bflag/cnt zeroing folded into kernels
//  - keeps: fp16 feat gather, dual-B GEMM, forked CSR, lookback scan
// ---------------------------------------------------------------------------

#define MAXN 50176
#define MAXE 860160

__device__ int      g_cnt[MAXN];
__device__ int      g_off[MAXN + 1];
__device__ int      g_pos[MAXN];
__device__ int      g_bflag[64];
__device__ int      g_csrc[MAXE];
__device__ __half   g_featH[MAXN * 128];
__device__ float    g_res [MAXN * 128];
__device__ float    g_h1  [MAXN * 128];
__device__ uint32_t g_h1hi[MAXN * 64], g_h1lo[MAXN * 64];
__device__ float    g_el  [MAXN * 4];
__device__ float    g_er  [MAXN * 4];
__device__ float    g_f3p [MAXN * 8];
__device__ float    g_er3p[MAXN * 8];
__device__ float    g_rb3 [MAXN];
__device__ uint32_t g_w1hi[128 * 32], g_w1lo[128 * 32];    // K=64  -> 32 pairs
__device__ uint32_t g_w2hi[128 * 64], g_w2lo[128 * 64];    // K=128 -> 64 pairs
__device__ uint32_t g_r2hi[128 * 64], g_r2lo[128 * 64];

// --------------------------- bf16 split helpers ----------------------------

__device__ __forceinline__ void split2(float x, float y, uint32_t& h, uint32_t& l) {
    __nv_bfloat162 hh = __floats2bfloat162_rn(x, y);          // low 16 = x
    float hx = __bfloat162float(hh.x), hy = __bfloat162float(hh.y);
    __nv_bfloat162 ll = __floats2bfloat162_rn(x - hx, y - hy);
    h = *reinterpret_cast<uint32_t*>(&hh);
    l = *reinterpret_cast<uint32_t*>(&ll);
}

__device__ __forceinline__ void mma16816(float* c, const uint32_t* a,
                                         uint32_t b0, uint32_t b1) {
    asm volatile(
        "mma.sync.aligned.m16n8k16.row.col.f32.bf16.bf16.f32 "
        "{%0,%1,%2,%3}, {%4,%5,%6,%7}, {%8,%9}, {%0,%1,%2,%3};\n"
        : "+f"(c[0]), "+f"(c[1]), "+f"(c[2]), "+f"(c[3])
        : "r"(a[0]), "r"(a[1]), "r"(a[2]), "r"(a[3]), "r"(b0), "r"(b1));
}

__global__ void k_prepW1(const float* __restrict__ W1) {
    int idx = blockIdx.x * 256 + threadIdx.x;
    if (idx >= 4096) return;
    int kk = idx >> 7, nn = idx & 127;
    float w0 = W1[(2 * kk) * 128 + nn];
    float w1 = W1[(2 * kk + 1) * 128 + nn];
    uint32_t h, l;
    split2(w0, w1, h, l);
    g_w1hi[nn * 32 + kk] = h;
    g_w1lo[nn * 32 + kk] = l;
}

__global__ void k_prepW2(const float* __restrict__ W2, const float* __restrict__ rW2) {
    int idx = blockIdx.x * 256 + threadIdx.x;
    if (idx >= 16384) return;
    const float* W = (idx < 8192) ? W2 : rW2;
    uint32_t* H = (idx < 8192) ? g_w2hi : g_r2hi;
    uint32_t* L = (idx < 8192) ? g_w2lo : g_r2lo;
    int local = idx & 8191;
    int kk = local >> 7, nn = local & 127;
    float w0 = W[(2 * kk) * 128 + nn];
    float w1 = W[(2 * kk + 1) * 128 + nn];
    uint32_t h, l;
    split2(w0, w1, h, l);
    H[nn * 64 + kk] = h;
    L[nn * 64 + kk] = l;
}

// ------------------------------ CSR build ---------------------------------

__global__ void k_hist(const int* __restrict__ dst, int E) {
    if (blockIdx.x == 0 && threadIdx.x < 64) g_bflag[threadIdx.x] = 0;
    int i = (blockIdx.x * blockDim.x + threadIdx.x) * 4;
    if (i + 3 < E) {
        int4 d = *(const int4*)(dst + i);
        atomicAdd(&g_cnt[d.x], 1);
        atomicAdd(&g_cnt[d.y], 1);
        atomicAdd(&g_cnt[d.z], 1);
        atomicAdd(&g_cnt[d.w], 1);
    } else {
        for (int j = i; j < E; j++) atomicAdd(&g_cnt[dst[j]], 1);
    }
}

// single-pass exclusive scan with lookback (all blocks resident).
__global__ void k_scan2(int n, int E) {
    __shared__ int ws[32];
    __shared__ int pre_s;
    int t = threadIdx.x, lane = t & 31, wid = t >> 5, b = blockIdx.x;
    int i = b * 1024 + t;
    int v = (i < n) ? g_cnt[i] : 0;
    int x = v;
    #pragma unroll
    for (int d = 1; d < 32; d <<= 1) {
        int y = __shfl_up_sync(0xffffffffu, x, d);
        if (lane >= d) x += y;
    }
    if (lane == 31) ws[wid] = x;
    __syncthreads();
    if (wid == 0) {
        int s = ws[lane];
        #pragma unroll
        for (int d = 1; d < 32; d <<= 1) {
            int y = __shfl_up_sync(0xffffffffu, s, d);
            if (lane >= d) s += y;
        }
        ws[lane] = s;
    }
    __syncthreads();
    int incl = x + (wid > 0 ? ws[wid - 1] : 0);
    if (t == 1023) atomicExch(&g_bflag[b], incl + 1);
    if (wid == 0) {
        int s = 0;
        for (int j = lane; j < b; j += 32) {
            int f;
            while ((f = atomicAdd(&g_bflag[j], 0)) == 0) { }
            s += f - 1;
        }
        #pragma unroll
        for (int o = 16; o > 0; o >>= 1) s += __shfl_xor_sync(0xffffffffu, s, o);
        if (lane == 0) pre_s = s;
    }
    __syncthreads();
    if (i < n) {
        int o = incl - v + pre_s;
        g_off[i] = o;
        g_pos[i] = o;
    }
    if (b == 0 && t == 0) g_off[n] = E;
}

// scatter + zero cnt for the next (deterministic) launch
__global__ void k_scatter(const int* __restrict__ src, const int* __restrict__ dst,
                          int E, int n) {
    int gid = blockIdx.x * blockDim.x + threadIdx.x;
    if (gid < n) g_cnt[gid] = 0;
    int i = gid * 4;
    if (i + 3 < E) {
        int4 s = *(const int4*)(src + i);
        int4 d = *(const int4*)(dst + i);
        int p0 = atomicAdd(&g_pos[d.x], 1);
        int p1 = atomicAdd(&g_pos[d.y], 1);
        int p2 = atomicAdd(&g_pos[d.z], 1);
        int p3 = atomicAdd(&g_pos[d.w], 1);
        g_csrc[p0] = s.x; g_csrc[p1] = s.y; g_csrc[p2] = s.z; g_csrc[p3] = s.w;
    } else {
        for (int j = i; j < E; j++) {
            int p = atomicAdd(&g_pos[dst[j]], 1);
            g_csrc[p] = src[j];
        }
    }
}

// ---------------- layer-1 GEMM: featH[M x 128] = x @ W1 + el/er ------------

__launch_bounds__(256, 2)
__global__ void k_gemm1(const float* __restrict__ A, int M,
                        const float* __restrict__ alv,
                        const float* __restrict__ arv) {
    const int K = 64, NP = 32;
    __shared__ uint32_t sAhi[128 * 20], sAlo[128 * 20];
    __shared__ uint32_t sBhi[128 * 20], sBlo[128 * 20];
    __shared__ float sEl[512], sEr[512], sAl[128], sAr[128];
    const int t = threadIdx.x;
    const int rowBase = blockIdx.x * 128;
    const int wid = t >> 5, lane = t & 31;
    const int mwarp = wid >> 1, nwarp = wid & 1;
    const int g = lane >> 2, tig = lane & 3;

    if (t < 128) { sAl[t] = alv[t]; sAr[t] = arv[t]; }

    float c[2][8][4];
    #pragma unroll
    for (int mi = 0; mi < 2; mi++)
        #pragma unroll
        for (int ni = 0; ni < 8; ni++)
            #pragma unroll
            for (int j = 0; j < 4; j++) c[mi][ni][j] = 0.f;

    for (int k0 = 0; k0 < K; k0 += 32) {
        const int kk0 = k0 >> 1;
        #pragma unroll
        for (int i = 0; i < 4; i++) {
            int idx = t + i * 256;
            int r = idx >> 3, c4 = idx & 7;
            int gr = rowBase + r;
            float4 v = make_float4(0.f, 0.f, 0.f, 0.f);
            if (gr < M) v = *(const float4*)(A + (size_t)gr * K + k0 + c4 * 4);
            uint32_t h0, l0, h1, l1;
            split2(v.x, v.y, h0, l0);
            split2(v.z, v.w, h1, l1);
            int b = r * 20 + c4 * 2;
            sAhi[b] = h0; sAlo[b] = l0;
            sAhi[b + 1] = h1; sAlo[b + 1] = l1;
        }
        #pragma unroll
        for (int i = 0; i < 2; i++) {
            int idx = t + i * 256;
            int nn = idx >> 2, j = (idx & 3) * 4;
            uint4 vh = *(const uint4*)(g_w1hi + nn * NP + kk0 + j);
            uint4 vl = *(const uint4*)(g_w1lo + nn * NP + kk0 + j);
            int b = nn * 20 + j;
            sBhi[b] = vh.x; sBhi[b + 1] = vh.y; sBhi[b + 2] = vh.z; sBhi[b + 3] = vh.w;
            sBlo[b] = vl.x; sBlo[b + 1] = vl.y; sBlo[b + 2] = vl.z; sBlo[b + 3] = vl.w;
        }
        __syncthreads();
        #pragma unroll
        for (int ks = 0; ks < 2; ks++) {
            const int ko = ks * 8;
            uint32_t ah[2][4], al_[2][4];
            #pragma unroll
            for (int mi = 0; mi < 2; mi++) {
                int base = (mwarp * 32 + mi * 16 + g) * 20 + ko + tig;
                ah[mi][0] = sAhi[base];        al_[mi][0] = sAlo[base];
                ah[mi][1] = sAhi[base + 160];  al_[mi][1] = sAlo[base + 160];
                ah[mi][2] = sAhi[base + 4];    al_[mi][2] = sAlo[base + 4];
                ah[mi][3] = sAhi[base + 164];  al_[mi][3] = sAlo[base + 164];
            }
            #pragma unroll
            for (int ni = 0; ni < 8; ni++) {
                int bb = (nwarp * 64 + ni * 8 + g) * 20 + ko + tig;
                uint32_t bh0 = sBhi[bb], bh1 = sBhi[bb + 4];
                uint32_t bl0 = sBlo[bb], bl1 = sBlo[bb + 4];
                #pragma unroll
                for (int mi = 0; mi < 2; mi++) {
                    mma16816(c[mi][ni], ah[mi], bh0, bh1);
                    mma16816(c[mi][ni], ah[mi], bl0, bl1);
                    mma16816(c[mi][ni], al_[mi], bh0, bh1);
                }
            }
        }
        __syncthreads();
    }
    #pragma unroll
    for (int mi = 0; mi < 2; mi++) {
        int r0 = rowBase + mwarp * 32 + mi * 16 + g;
        #pragma unroll
        for (int ni = 0; ni < 8; ni++) {
            int col = nwarp * 64 + ni * 8 + tig * 2;
            if (r0 < M)
                *(__half2*)(g_featH + (size_t)r0 * 128 + col) =
                    __floats2half2_rn(c[mi][ni][0], c[mi][ni][1]);
            if (r0 + 8 < M)
                *(__half2*)(g_featH + (size_t)(r0 + 8) * 128 + col) =
                    __floats2half2_rn(c[mi][ni][2], c[mi][ni][3]);
        }
    }
    #pragma unroll
    for (int mi = 0; mi < 2; mi++) {
        float pel[2][2] = {{0.f, 0.f}, {0.f, 0.f}};
        float per_[2][2] = {{0.f, 0.f}, {0.f, 0.f}};
        #pragma unroll
        for (int ni = 0; ni < 8; ni++) {
            int col = nwarp * 64 + ni * 8 + tig * 2;
            int hh = ni >> 2;
            float a0 = sAl[col], a1 = sAl[col + 1];
            float r0 = sAr[col], r1 = sAr[col + 1];
            pel[0][hh] += c[mi][ni][0] * a0 + c[mi][ni][1] * a1;
            per_[0][hh] += c[mi][ni][0] * r0 + c[mi][ni][1] * r1;
            pel[1][hh] += c[mi][ni][2] * a0 + c[mi][ni][3] * a1;
            per_[1][hh] += c[mi][ni][2] * r0 + c[mi][ni][3] * r1;
        }
        #pragma unroll
        for (int gg = 0; gg < 2; gg++)
            #pragma unroll
            for (int hh = 0; hh < 2; hh++) {
                float v = pel[gg][hh], w = per_[gg][hh];
                v += __shfl_xor_sync(0xffffffffu, v, 1);
                v += __shfl_xor_sync(0xffffffffu, v, 2);
                w += __shfl_xor_sync(0xffffffffu, w, 1);
                w += __shfl_xor_sync(0xffffffffu, w, 2);
                if (tig == 0) {
                    int r = mwarp * 32 + mi * 16 + g + gg * 8;
                    sEl[r * 4 + nwarp * 2 + hh] = v;
                    sEr[r * 4 + nwarp * 2 + hh] = w;
                }
            }
    }
    __syncthreads();
    #pragma unroll
    for (int i0 = 0; i0 < 2; i0++) {
        int i = t + i0 * 256;
        int gr = rowBase + (i >> 2);
        if (gr < M) {
            g_el[gr * 4 + (i & 3)] = sEl[i];
            g_er[gr * 4 + (i & 3)] = sEr[i];
        }
    }
}

// --------- layer-2 dual GEMM: featH = h1@W2 (+el/er), res = h1@rW2 ---------
// A arrives pre-split (hi/lo bf16x2 pairs written by agg4-L1 epilogue).

#define ASTRIDE 68

__launch_bounds__(256, 2)
__global__ void k_gemm2dual(int M, const float* __restrict__ alv,
                            const float* __restrict__ arv) {
    extern __shared__ uint32_t sm[];
    uint32_t* sAhi = sm;                        // 128*ASTRIDE
    uint32_t* sAlo = sAhi + 128 * ASTRIDE;
    uint32_t* sBhi = sAlo + 128 * ASTRIDE;      // 128*20
    uint32_t* sBlo = sBhi + 128 * 20;
    float* sEl = (float*)(sBlo + 128 * 20);     // 512
    float* sEr = sEl + 512;
    float* sAl = sEr + 512;                     // 128
    float* sAr = sAl + 128;

    const int t = threadIdx.x;
    const int rowBase = blockIdx.x * 128;
    const int wid = t >> 5, lane = t & 31;
    const int mwarp = wid >> 1, nwarp = wid & 1;
    const int g = lane >> 2, tig = lane & 3;

    if (t < 128) { sAl[t] = alv[t]; sAr[t] = arv[t]; }

    // copy pre-split A tile: 128 rows x 16 uint4 per array
    const uint4* Ahi = (const uint4*)g_h1hi;
    const uint4* Alo = (const uint4*)g_h1lo;
    #pragma unroll
    for (int i = 0; i < 8; i++) {
        int idx = t + i * 256;
        int r = idx >> 4, j = idx & 15;
        int gr = rowBase + r;
        uint4 vh = make_uint4(0u, 0u, 0u, 0u), vl = make_uint4(0u, 0u, 0u, 0u);
        if (gr < M) {
            vh = Ahi[(size_t)gr * 16 + j];
            vl = Alo[(size_t)gr * 16 + j];
        }
        *(uint4*)&sAhi[r * ASTRIDE + j * 4] = vh;
        *(uint4*)&sAlo[r * ASTRIDE + j * 4] = vl;
    }

    #pragma unroll
    for (int bmat = 0; bmat < 2; bmat++) {
        const uint32_t* Whi = bmat ? g_r2hi : g_w2hi;
        const uint32_t* Wlo = bmat ? g_r2lo : g_w2lo;
        float c[2][8][4];
        #pragma unroll
        for (int mi = 0; mi < 2; mi++)
            #pragma unroll
            for (int ni = 0; ni < 8; ni++)
                #pragma unroll
                for (int j = 0; j < 4; j++) c[mi][ni][j] = 0.f;

        for (int kt = 0; kt < 4; kt++) {
            __syncthreads();
            #pragma unroll
            for (int i = 0; i < 2; i++) {
                int idx = t + i * 256;
                int nn = idx >> 2, j = (idx & 3) * 4;
                uint4 vh = *(const uint4*)(Whi + nn * 64 + kt * 16 + j);
                uint4 vl = *(const uint4*)(Wlo + nn * 64 + kt * 16 + j);
                int b = nn * 20 + j;
                sBhi[b] = vh.x; sBhi[b + 1] = vh.y; sBhi[b + 2] = vh.z; sBhi[b + 3] = vh.w;
                sBlo[b] = vl.x; sBlo[b + 1] = vl.y; sBlo[b + 2] = vl.z; sBlo[b + 3] = vl.w;
            }
            __syncthreads();
            #pragma unroll
            for (int ks = 0; ks < 2; ks++) {
                const int ko = ks * 8;
                uint32_t ah[2][4], al_[2][4];
                #pragma unroll
                for (int mi = 0; mi < 2; mi++) {
                    int base = (mwarp * 32 + mi * 16 + g) * ASTRIDE + kt * 16 + ko + tig;
                    ah[mi][0] = sAhi[base];                   al_[mi][0] = sAlo[base];
                    ah[mi][1] = sAhi[base + 8 * ASTRIDE];     al_[mi][1] = sAlo[base + 8 * ASTRIDE];
                    ah[mi][2] = sAhi[base + 4];               al_[mi][2] = sAlo[base + 4];
                    ah[mi][3] = sAhi[base + 8 * ASTRIDE + 4]; al_[mi][3] = sAlo[base + 8 * ASTRIDE + 4];
                }
                #pragma unroll
                for (int ni = 0; ni < 8; ni++) {
                    int bb = (nwarp * 64 + ni * 8 + g) * 20 + ko + tig;
                    uint32_t bh0 = sBhi[bb], bh1 = sBhi[bb + 4];
                    uint32_t bl0 = sBlo[bb], bl1 = sBlo[bb + 4];
                    #pragma unroll
                    for (int mi = 0; mi < 2; mi++) {
                        mma16816(c[mi][ni], ah[mi], bh0, bh1);
                        mma16816(c[mi][ni], ah[mi], bl0, bl1);
                        mma16816(c[mi][ni], al_[mi], bh0, bh1);
                    }
                }
            }
        }

        if (bmat == 0) {
            #pragma unroll
            for (int mi = 0; mi < 2; mi++) {
                int r0 = rowBase + mwarp * 32 + mi * 16 + g;
                #pragma unroll
                for (int ni = 0; ni < 8; ni++) {
                    int col = nwarp * 64 + ni * 8 + tig * 2;
                    if (r0 < M)
                        *(__half2*)(g_featH + (size_t)r0 * 128 + col) =
                            __floats2half2_rn(c[mi][ni][0], c[mi][ni][1]);
                    if (r0 + 8 < M)
                        *(__half2*)(g_featH + (size_t)(r0 + 8) * 128 + col) =
                            __floats2half2_rn(c[mi][ni][2], c[mi][ni][3]);
                }
            }
            #pragma unroll
            for (int mi = 0; mi < 2; mi++) {
                float pel[2][2] = {{0.f, 0.f}, {0.f, 0.f}};
                float per_[2][2] = {{0.f, 0.f}, {0.f, 0.f}};
                #pragma unroll
                for (int ni = 0; ni < 8; ni++) {
                    int col = nwarp * 64 + ni * 8 + tig * 2;
                    int hh = ni >> 2;
                    float a0 = sAl[col], a1 = sAl[col + 1];
                    float r0 = sAr[col], r1 = sAr[col + 1];
                    pel[0][hh] += c[mi][ni][0] * a0 + c[mi][ni][1] * a1;
                    per_[0][hh] += c[mi][ni][0] * r0 + c[mi][ni][1] * r1;
                    pel[1][hh] += c[mi][ni][2] * a0 + c[mi][ni][3] * a1;
                    per_[1][hh] += c[mi][ni][2] * r0 + c[mi][ni][3] * r1;
                }
                #pragma unroll
                for (int gg = 0; gg < 2; gg++)
                    #pragma unroll
                    for (int hh = 0; hh < 2; hh++) {
                        float v = pel[gg][hh], w = per_[gg][hh];
                        v += __shfl_xor_sync(0xffffffffu, v, 1);
                        v += __shfl_xor_sync(0xffffffffu, v, 2);
                        w += __shfl_xor_sync(0xffffffffu, w, 1);
                        w += __shfl_xor_sync(0xffffffffu, w, 2);
                        if (tig == 0) {
                            int r = mwarp * 32 + mi * 16 + g + gg * 8;
                            sEl[r * 4 + nwarp * 2 + hh] = v;
                            sEr[r * 4 + nwarp * 2 + hh] = w;
                        }
                    }
            }
            __syncthreads();
            #pragma unroll
            for (int i0 = 0; i0 < 2; i0++) {
                int i = t + i0 * 256;
                int gr = rowBase + (i >> 2);
                if (gr < M) {
                    g_el[gr * 4 + (i & 3)] = sEl[i];
                    g_er[gr * 4 + (i & 3)] = sEr[i];
                }
            }
        } else {
            #pragma unroll
            for (int mi = 0; mi < 2; mi++) {
                int r0 = rowBase + mwarp * 32 + mi * 16 + g;
                #pragma unroll
                for (int ni = 0; ni < 8; ni++) {
                    int col = nwarp * 64 + ni * 8 + tig * 2;
                    if (r0 < M)
                        *(float2*)(g_res + (size_t)r0 * 128 + col) =
                            make_float2(c[mi][ni][0], c[mi][ni][1]);
                    if (r0 + 8 < M)
                        *(float2*)(g_res + (size_t)(r0 + 8) * 128 + col) =
                            make_float2(c[mi][ni][2], c[mi][ni][3]);
                }
            }
        }
    }
}

// -------------- warp-per-node aggregation, H=4 D=32, 1 pass ----------------
// Logit phase: lane = 4*eo+h over 8 edges. Gather: 16 lanes/edge, LDG.128,
// 2 edges per iteration. MODE 0: L1 (no res; pre-split bf16 output).
// MODE 1: L2 (res; fp32 output for l3gemm).

template <int MODE>
__launch_bounds__(256)
__global__ void k_agg4(const float4* __restrict__ res4,
                       const float4* __restrict__ bias4, int n) {
    int node = blockIdx.x * 8 + (threadIdx.x >> 5);
    if (node >= n) return;
    const int lane = threadIdx.x & 31;
    const int h = lane & 3, eo = lane >> 2;
    const int li = lane & 15, half = lane >> 4, hd = li >> 2;
    int rs = g_off[node], re = g_off[node + 1];
    float er_h = g_er[node * 4 + h];
    const uint4* featH4 = (const uint4*)g_featH;

    float acc[8];
    #pragma unroll
    for (int j = 0; j < 8; j++) acc[j] = 0.f;
    float den = 0.f;

    int b = rs;
    for (; b + 8 <= re; b += 8) {
        int s = g_csrc[b + eo];
        float v = g_el[s * 4 + h] + er_h;
        v = v > 0.f ? v : 0.2f * v;
        float ee = __expf(v);
        den += ee;
        #pragma unroll
        for (int q = 0; q < 4; q++) {
            int esl = (q * 2 + half) * 4;
            int   sq = __shfl_sync(0xffffffffu, s, esl);
            float eq = __shfl_sync(0xffffffffu, ee, esl + hd);
            uint4 u = featH4[(size_t)sq * 16 + li];
            const __half2* hp = reinterpret_cast<const __half2*>(&u);
            float2 f0 = __half22float2(hp[0]);
            float2 f1 = __half22float2(hp[1]);
            float2 f2 = __half22float2(hp[2]);
            float2 f3 = __half22float2(hp[3]);
            acc[0] = fmaf(eq, f0.x, acc[0]);
            acc[1] = fmaf(eq, f0.y, acc[1]);
            acc[2] = fmaf(eq, f1.x, acc[2]);
            acc[3] = fmaf(eq, f1.y, acc[3]);
            acc[4] = fmaf(eq, f2.x, acc[4]);
            acc[5] = fmaf(eq, f2.y, acc[5]);
            acc[6] = fmaf(eq, f3.x, acc[6]);
            acc[7] = fmaf(eq, f3.y, acc[7]);
        }
    }
    if (b < re) {
        int bc = re - b;
        int e = b + eo;
        int s = 0;
        float ee = 0.f;
        if (e < re) {
            s = g_csrc[e];
            float v = g_el[s * 4 + h] + er_h;
            v = v > 0.f ? v : 0.2f * v;
            ee = __expf(v);
            den += ee;
        }
        int qmax = (bc + 1) >> 1;          // warp-uniform
        for (int q = 0; q < qmax; q++) {
            int esl = (q * 2 + half) * 4;
            int   sq = __shfl_sync(0xffffffffu, s, esl);
            float eq = __shfl_sync(0xffffffffu, ee, esl + hd);  // 0 if invalid
            uint4 u = featH4[(size_t)sq * 16 + li];
            const __half2* hp = reinterpret_cast<const __half2*>(&u);
            float2 f0 = __half22float2(hp[0]);
            float2 f1 = __half22float2(hp[1]);
            float2 f2 = __half22float2(hp[2]);
            float2 f3 = __half22float2(hp[3]);
            acc[0] = fmaf(eq, f0.x, acc[0]);
            acc[1] = fmaf(eq, f0.y, acc[1]);
            acc[2] = fmaf(eq, f1.x, acc[2]);
            acc[3] = fmaf(eq, f1.y, acc[3]);
            acc[4] = fmaf(eq, f2.x, acc[4]);
            acc[5] = fmaf(eq, f2.y, acc[5]);
            acc[6] = fmaf(eq, f3.x, acc[6]);
            acc[7] = fmaf(eq, f3.y, acc[7]);
        }
    }
    den += __shfl_xor_sync(0xffffffffu, den, 16);
    den += __shfl_xor_sync(0xffffffffu, den, 8);
    den += __shfl_xor_sync(0xffffffffu, den, 4);
    float inv = 1.f / __shfl_sync(0xffffffffu, den, hd);
    #pragma unroll
    for (int j = 0; j < 8; j++)
        acc[j] += __shfl_xor_sync(0xffffffffu, acc[j], 16);

    if (half == 0) {
        float4 b0 = bias4[2 * li], b1 = bias4[2 * li + 1];
        float o[8];
        o[0] = acc[0] * inv + b0.x; o[1] = acc[1] * inv + b0.y;
        o[2] = acc[2] * inv + b0.z; o[3] = acc[3] * inv + b0.w;
        o[4] = acc[4] * inv + b1.x; o[5] = acc[5] * inv + b1.y;
        o[6] = acc[6] * inv + b1.z; o[7] = acc[7] * inv + b1.w;
        if (MODE == 1) {
            float4 r0 = res4[(size_t)node * 32 + 2 * li];
            float4 r1 = res4[(size_t)node * 32 + 2 * li + 1];
            o[0] += r0.x; o[1] += r0.y; o[2] += r0.z; o[3] += r0.w;
            o[4] += r1.x; o[5] += r1.y; o[6] += r1.z; o[7] += r1.w;
        }
        #pragma unroll
        for (int j = 0; j < 8; j++) o[j] = fmaxf(o[j], 0.f);
        if (MODE == 1) {
            ((float4*)g_h1)[(size_t)node * 32 + 2 * li] = make_float4(o[0], o[1], o[2], o[3]);
            ((float4*)g_h1)[(size_t)node * 32 + 2 * li + 1] = make_float4(o[4], o[5], o[6], o[7]);
        } else {
            uint32_t H[4], L[4];
            split2(o[0], o[1], H[0], L[0]);
            split2(o[2], o[3], H[1], L[1]);
            split2(o[4], o[5], H[2], L[2]);
            split2(o[6], o[7], H[3], L[3]);
            ((uint4*)g_h1hi)[(size_t)node * 16 + li] = make_uint4(H[0], H[1], H[2], H[3]);
            ((uint4*)g_h1lo)[(size_t)node * 16 + li] = make_uint4(L[0], L[1], L[2], L[3]);
        }
    }
}

// ---------------------- layer 3: fused small GEMM --------------------------

__global__ void k_l3gemm(const float* __restrict__ W3,
                         const float* __restrict__ rW3, const float* __restrict__ ar3,
                         const float* __restrict__ b3, int n) {
    __shared__ float sW[768], sR[768];
    int t = threadIdx.x;
    for (int i = t; i < 768; i += 256) { sW[i] = W3[i]; sR[i] = rW3[i]; }
    __syncthreads();
    int node = blockIdx.x * 256 + t;
    if (node >= n) return;
    const float4* hr = (const float4*)(g_h1 + (size_t)node * 128);
    float acc[6] = {0.f, 0.f, 0.f, 0.f, 0.f, 0.f};
    float rac[6] = {0.f, 0.f, 0.f, 0.f, 0.f, 0.f};
    #pragma unroll 8
    for (int k4 = 0; k4 < 32; k4++) {
        float4 a = hr[k4];
        int k = k4 * 4;
        #pragma unroll
        for (int j = 0; j < 6; j++) {
            acc[j] += a.x * sW[(k + 0) * 6 + j] + a.y * sW[(k + 1) * 6 + j]
                    + a.z * sW[(k + 2) * 6 + j] + a.w * sW[(k + 3) * 6 + j];
            rac[j] += a.x * sR[(k + 0) * 6 + j] + a.y * sR[(k + 1) * 6 + j]
                    + a.z * sR[(k + 2) * 6 + j] + a.w * sR[(k + 3) * 6 + j];
        }
    }
    float rb = 0.f;
    #pragma unroll
    for (int j = 0; j < 6; j++) {
        g_f3p [node * 8 + j] = acc[j];
        g_er3p[node * 8 + j] = acc[j] * ar3[j];
        rb += rac[j] + b3[j];
    }
    g_f3p [node * 8 + 6] = 0.f; g_f3p [node * 8 + 7] = 0.f;
    g_er3p[node * 8 + 6] = 0.f; g_er3p[node * 8 + 7] = 0.f;
    g_rb3[node] = rb;
}

// --------- layer 3 aggregation (H=6, D=1) + head mean, single pass ---------

__global__ void k_agg3(const float* __restrict__ al3, float* __restrict__ out, int n) {
    int node = blockIdx.x * 8 + (threadIdx.x >> 5);
    if (node >= n) return;
    int lane = threadIdx.x & 31;
    int rs = g_off[node], re = g_off[node + 1];
    float al[6];
    #pragma unroll
    for (int j = 0; j < 6; j++) al[j] = al3[j];
    float4 e0 = *(const float4*)(g_er3p + (size_t)node * 8);
    float4 e1 = *(const float4*)(g_er3p + (size_t)node * 8 + 4);
    float erh[6] = {e0.x, e0.y, e0.z, e0.w, e1.x, e1.y};

    float acc[6], den[6];
    #pragma unroll
    for (int j = 0; j < 6; j++) { acc[j] = 0.f; den[j] = 0.f; }
    for (int e = rs + lane; e < re; e += 32) {
        int s = g_csrc[e];
        float4 f0 = *(const float4*)(g_f3p + (size_t)s * 8);
        float4 f1 = *(const float4*)(g_f3p + (size_t)s * 8 + 4);
        float f[6] = {f0.x, f0.y, f0.z, f0.w, f1.x, f1.y};
        #pragma unroll
        for (int j = 0; j < 6; j++) {
            float v = fmaf(f[j], al[j], erh[j]);
            v = v > 0.f ? v : 0.2f * v;
            float ee = __expf(v);
            den[j] += ee;
            acc[j] = fmaf(ee, f[j], acc[j]);
        }
    }
    #pragma unroll
    for (int j = 0; j < 6; j++) {
        #pragma unroll
        for (int o = 16; o > 0; o >>= 1) {
            acc[j] += __shfl_xor_sync(0xffffffffu, acc[j], o);
            den[j] += __shfl_xor_sync(0xffffffffu, den[j], o);
        }
    }
    if (lane == 0) {
        float o_ = 0.f;
        #pragma unroll
        for (int j = 0; j < 6; j++) o_ += acc[j] / den[j];
        out[node] = (o_ + g_rb3[node]) * (1.f / 6.f);
    }
}

// ------------------------------- launcher ----------------------------------

#define G2_SMEM ((128 * ASTRIDE * 2 + 128 * 20 * 2) * 4 + (512 * 2 + 128 * 2) * 4)

extern "C" void kernel_launch(void* const* d_in, const int* in_sizes, int n_in,
                              void* d_out, int out_size) {
    const float* x   = (const float*)d_in[0];
    const int*   src = (const int*)  d_in[1];
    const int*   dst = (const int*)  d_in[2];
    const float* W1  = (const float*)d_in[3];
    const float* al1 = (const float*)d_in[4];
    const float* ar1 = (const float*)d_in[5];
    const float* b1  = (const float*)d_in[6];
    const float* W2  = (const float*)d_in[7];
    const float* al2 = (const float*)d_in[8];
    const float* ar2 = (const float*)d_in[9];
    const float* b2  = (const float*)d_in[10];
    const float* rW2 = (const float*)d_in[11];
    const float* W3  = (const float*)d_in[12];
    const float* al3 = (const float*)d_in[13];
    const float* ar3 = (const float*)d_in[14];
    const float* b3  = (const float*)d_in[15];
    const float* rW3 = (const float*)d_in[16];
    int n = in_sizes[0] / 64;
    int E = in_sizes[1];
    float* out = (float*)d_out;

    float* res;
    cudaGetSymbolAddress((void**)&res, g_res);

    static cudaStream_t s2 = nullptr, s3 = nullptr;
    static cudaEvent_t evFork = nullptr, evJoin = nullptr, evPrep2 = nullptr;
    if (!s2) {
        cudaStreamCreateWithFlags(&s2, cudaStreamNonBlocking);
        cudaStreamCreateWithFlags(&s3, cudaStreamNonBlocking);
        cudaEventCreateWithFlags(&evFork, cudaEventDisableTiming);
        cudaEventCreateWithFlags(&evJoin, cudaEventDisableTiming);
        cudaEventCreateWithFlags(&evPrep2, cudaEventDisableTiming);
        cudaFuncSetAttribute(k_gemm2dual,
                             cudaFuncAttributeMaxDynamicSharedMemorySize, G2_SMEM);
    }

    int nb = (n + 1023) / 1024;
    int gb = (n + 127) / 128;
    int ab = (n + 7) / 8;

    // --- fork: CSR on s2, prepW2 on s3, prepW1 + GEMM1 on main ---
    cudaEventRecord(evFork, 0);
    cudaStreamWaitEvent(s2, evFork, 0);
    cudaStreamWaitEvent(s3, evFork, 0);

    k_hist   <<<(E + 1023) / 1024, 256, 0, s2>>>(dst, E);
    k_scan2  <<<nb, 1024, 0, s2>>>(n, E);
    k_scatter<<<(E + 1023) / 1024, 256, 0, s2>>>(src, dst, E, n);
    cudaEventRecord(evJoin, s2);

    k_prepW2<<<64, 256, 0, s3>>>(W2, rW2);
    cudaEventRecord(evPrep2, s3);

    k_prepW1<<<16, 256>>>(W1);
    k_gemm1<<<gb, 256>>>(x, n, al1, ar1);

    cudaStreamWaitEvent(0, evJoin, 0);

    // --- layer 1 aggregate -> pre-split h1 pairs ---
    k_agg4<0><<<ab, 256>>>((const float4*)nullptr, (const float4*)b1, n);

    cudaStreamWaitEvent(0, evPrep2, 0);

    // --- layer 2: dual GEMM (+el/er), aggregate -> h1 (fp32) ---
    k_gemm2dual<<<gb, 256, G2_SMEM>>>(n, al2, ar2);
    k_agg4<1><<<ab, 256>>>((const float4*)res, (const float4*)b2, n);

    // --- layer 3: projection + aggregation -> output ---
    k_l3gemm<<<(n + 255) / 256, 256>>>(W3, rW3, ar3, b3, n);
    k_agg3<<<ab, 256>>>(al3, out, n);
}